// round 2
// baseline (speedup 1.0000x reference)
#include <cuda_runtime.h>
#include <cstdint>
#include <cstddef>

#define B_  2
#define S_  2048
#define D_  1024
#define H_  16
#define HD_ 64

#define NEG_INF (__int_as_float(0xff800000))

// 16 MB each — static device scratch (allocation-free rule)
__device__ float g_q[(size_t)B_ * H_ * S_ * HD_];
__device__ float g_k[(size_t)B_ * H_ * S_ * HD_];

// ---------------------------------------------------------------------------
// Kernel 1: qk = encoded @ W^T + bias ; scatter into g_q / g_k as [b][h][s][hd]
// (at the fp32 FFMA roofline already — unchanged this round)
// ---------------------------------------------------------------------------
#define BM 128
#define BN 128
#define BK 8

__global__ __launch_bounds__(256) void proj_kernel(
    const float* __restrict__ A,     // [4096, 1024]
    const float* __restrict__ W,     // [2048, 1024]
    const float* __restrict__ bias)  // [2048]
{
    __shared__ float As[BK][BM + 4];
    __shared__ float Bs[BK][BN + 4];

    const int tid = threadIdx.x;
    const int m0  = blockIdx.y * BM;
    const int n0  = blockIdx.x * BN;
    const int tx  = tid & 15;
    const int ty  = tid >> 4;
    const int lrow = tid >> 1;          // 0..127
    const int lk4  = (tid & 1) << 2;    // 0 or 4

    const float* Ag = A + (size_t)(m0 + lrow) * D_ + lk4;
    const float* Wg = W + (size_t)(n0 + lrow) * D_ + lk4;

    float acc[8][8];
    #pragma unroll
    for (int i = 0; i < 8; i++)
        #pragma unroll
        for (int j = 0; j < 8; j++) acc[i][j] = 0.f;

    for (int k0 = 0; k0 < D_; k0 += BK) {
        float4 av = *(const float4*)(Ag + k0);
        float4 wv = *(const float4*)(Wg + k0);
        __syncthreads();
        As[lk4 + 0][lrow] = av.x; As[lk4 + 1][lrow] = av.y;
        As[lk4 + 2][lrow] = av.z; As[lk4 + 3][lrow] = av.w;
        Bs[lk4 + 0][lrow] = wv.x; Bs[lk4 + 1][lrow] = wv.y;
        Bs[lk4 + 2][lrow] = wv.z; Bs[lk4 + 3][lrow] = wv.w;
        __syncthreads();

        #pragma unroll
        for (int kk = 0; kk < BK; kk++) {
            float4 a0 = *(const float4*)&As[kk][ty * 8];
            float4 a1 = *(const float4*)&As[kk][ty * 8 + 4];
            float4 b0 = *(const float4*)&Bs[kk][tx * 8];
            float4 b1 = *(const float4*)&Bs[kk][tx * 8 + 4];
            float a[8] = {a0.x, a0.y, a0.z, a0.w, a1.x, a1.y, a1.z, a1.w};
            float b[8] = {b0.x, b0.y, b0.z, b0.w, b1.x, b1.y, b1.z, b1.w};
            #pragma unroll
            for (int i = 0; i < 8; i++)
                #pragma unroll
                for (int j = 0; j < 8; j++)
                    acc[i][j] = fmaf(a[i], b[j], acc[i][j]);
        }
    }

    // Epilogue: add bias, scatter to q/k scratch with [b][h][s][hd] layout.
    const int e0 = n0 + tx * 8;            // 8 consecutive e, same head block
    float bv[8];
    #pragma unroll
    for (int j = 0; j < 8; j++) bv[j] = bias[e0 + j];

    const bool is_q = (e0 < D_);
    const int  eh   = is_q ? e0 : (e0 - D_);
    const int  hh   = eh >> 6;
    const int  hd0  = eh & 63;
    float* dst = is_q ? g_q : g_k;

    #pragma unroll
    for (int i = 0; i < 8; i++) {
        const int m  = m0 + ty * 8 + i;
        const int bb = m >> 11;            // m / 2048
        const int s  = m & (S_ - 1);
        float* row = dst + (((size_t)bb * H_ + hh) * S_ + s) * HD_ + hd0;
        #pragma unroll
        for (int j = 0; j < 8; j++)
            row[j] = acc[i][j] + bv[j];
    }
}

// ---------------------------------------------------------------------------
// Kernel 2: causal scores + softmax. Block = 16 query rows for one (b,h).
// Loop nest restructured (hd4 outer): one broadcast q-LDS feeds 16 FFMAs
// (4 chunks) instead of 4 -> 4x fewer smem wavefronts, FMA-bound.
// ---------------------------------------------------------------------------
#define TQ 16

__global__ __launch_bounds__(512, 1) void attn_kernel(float* __restrict__ out)
{
    __shared__ float qs[TQ][68];        // stride 68: conflict-free float4
    __shared__ float red[16][17];
    __shared__ float rowmax_s[TQ];
    __shared__ float rowinv_s[TQ];

    const int tid = threadIdx.x;
    const int w   = tid >> 5;
    const int l   = tid & 31;
    const int t0  = blockIdx.x * TQ;
    const size_t bh = (size_t)blockIdx.z * H_ + blockIdx.y;

    const float* qg = g_q + (bh * S_ + t0) * HD_;
    const float* kg = g_k + bh * S_ * HD_;

    // Load Q tile (scale = 1/sqrt(64) folded into q)
    if (tid < 256) {
        const int r  = tid >> 4;
        const int c4 = (tid & 15) << 2;
        float4 v = *(const float4*)(qg + r * HD_ + c4);
        const float scale = 0.125f;
        v.x *= scale; v.y *= scale; v.z *= scale; v.w *= scale;
        *(float4*)&qs[r][c4] = v;
    }
    __syncthreads();

    const int nch = ((t0 + TQ - 1) >> 5) + 1;   // number of needed 32-wide s-chunks

    float sc[TQ][4];
    #pragma unroll
    for (int r = 0; r < TQ; r++)
        #pragma unroll
        for (int c = 0; c < 4; c++) sc[r][c] = 0.f;

    // K row for this lane in chunk c = w + 16*c : s = ((w + 16c)<<5) + l.
    // Max s = ((15+48)<<5)+31 = 2047 -> always in-bounds, load unconditionally.
    // Chunk-to-chunk stride: 16 chunks * 32 rows * 16 float4/row = 8192 float4.
    const float4* kr0 = (const float4*)(kg + (size_t)(((w << 5) + l)) * HD_);

    #pragma unroll 2
    for (int hd4 = 0; hd4 < 16; hd4++) {
        float4 kv0 = kr0[0 * 8192 + hd4];
        float4 kv1 = kr0[1 * 8192 + hd4];
        float4 kv2 = kr0[2 * 8192 + hd4];
        float4 kv3 = kr0[3 * 8192 + hd4];
        #pragma unroll
        for (int r = 0; r < TQ; r++) {
            const float4 qv = *(const float4*)&qs[r][hd4 << 2];
            sc[r][0] = fmaf(kv0.x, qv.x, sc[r][0]);
            sc[r][0] = fmaf(kv0.y, qv.y, sc[r][0]);
            sc[r][0] = fmaf(kv0.z, qv.z, sc[r][0]);
            sc[r][0] = fmaf(kv0.w, qv.w, sc[r][0]);
            sc[r][1] = fmaf(kv1.x, qv.x, sc[r][1]);
            sc[r][1] = fmaf(kv1.y, qv.y, sc[r][1]);
            sc[r][1] = fmaf(kv1.z, qv.z, sc[r][1]);
            sc[r][1] = fmaf(kv1.w, qv.w, sc[r][1]);
            sc[r][2] = fmaf(kv2.x, qv.x, sc[r][2]);
            sc[r][2] = fmaf(kv2.y, qv.y, sc[r][2]);
            sc[r][2] = fmaf(kv2.z, qv.z, sc[r][2]);
            sc[r][2] = fmaf(kv2.w, qv.w, sc[r][2]);
            sc[r][3] = fmaf(kv3.x, qv.x, sc[r][3]);
            sc[r][3] = fmaf(kv3.y, qv.y, sc[r][3]);
            sc[r][3] = fmaf(kv3.z, qv.z, sc[r][3]);
            sc[r][3] = fmaf(kv3.w, qv.w, sc[r][3]);
        }
    }

    // Causal mask + unvisited chunks -> -inf (exp -> exact 0, matching ref underflow)
    #pragma unroll
    for (int c = 0; c < 4; c++) {
        const int j = w + (c << 4);
        const int s = (j << 5) + l;
        #pragma unroll
        for (int r = 0; r < TQ; r++)
            if (j >= nch || s > t0 + r) sc[r][c] = NEG_INF;
    }

    // Row max: lane -> warp shfl -> cross-warp smem
    #pragma unroll
    for (int r = 0; r < TQ; r++) {
        float v = fmaxf(fmaxf(sc[r][0], sc[r][1]), fmaxf(sc[r][2], sc[r][3]));
        #pragma unroll
        for (int off = 16; off > 0; off >>= 1)
            v = fmaxf(v, __shfl_xor_sync(0xffffffffu, v, off));
        if (l == 0) red[w][r] = v;
    }
    __syncthreads();
    if (tid < TQ) {
        float v = red[0][tid];
        #pragma unroll
        for (int ww = 1; ww < 16; ww++) v = fmaxf(v, red[ww][tid]);
        rowmax_s[tid] = v;
    }
    __syncthreads();

    // exp + row sum
    #pragma unroll
    for (int r = 0; r < TQ; r++) {
        const float m = rowmax_s[r];
        float t = 0.f;
        #pragma unroll
        for (int c = 0; c < 4; c++) {
            const float e = __expf(sc[r][c] - m);
            sc[r][c] = e;
            t += e;
        }
        #pragma unroll
        for (int off = 16; off > 0; off >>= 1)
            t += __shfl_xor_sync(0xffffffffu, t, off);
        if (l == 0) red[w][r] = t;
    }
    __syncthreads();
    if (tid < TQ) {
        float v = 0.f;
        #pragma unroll
        for (int ww = 0; ww < 16; ww++) v += red[ww][tid];
        rowinv_s[tid] = 1.0f / v;
    }
    __syncthreads();

    float inv[TQ];
    #pragma unroll
    for (int r = 0; r < TQ; r++) inv[r] = rowinv_s[r];

    // Write: lane l covers s = 32*j + l -> 128B coalesced stores per (r, chunk)
    float* obase = out + (bh * S_ + t0) * (size_t)S_;
    #pragma unroll
    for (int c = 0; c < 4; c++) {
        const int j = w + (c << 4);
        const size_t so = (size_t)(j << 5) + l;
        #pragma unroll
        for (int r = 0; r < TQ; r++)
            obase[(size_t)r * S_ + so] = sc[r][c] * inv[r];
    }
}

// ---------------------------------------------------------------------------
extern "C" void kernel_launch(void* const* d_in, const int* in_sizes, int n_in,
                              void* d_out, int out_size)
{
    (void)in_sizes; (void)n_in; (void)out_size;
    const float* encoded = (const float*)d_in[0];  // [2, 2048, 1024]
    const float* W       = (const float*)d_in[1];  // [2048, 1024]
    const float* bias    = (const float*)d_in[2];  // [2048]
    float* out = (float*)d_out;                    // [2, 16, 2048, 2048]

    dim3 g1((2 * D_) / BN, (B_ * S_) / BM);        // (16, 32)
    proj_kernel<<<g1, 256>>>(encoded, W, bias);

    dim3 g2(S_ / TQ, H_, B_);                      // (128, 16, 2)
    attn_kernel<<<g2, 512>>>(out);
}

// round 5
// speedup vs baseline: 2.5918x; 2.5918x over previous
#include <cuda_runtime.h>
#include <cuda_bf16.h>
#include <cstdint>
#include <cstddef>

#define B_  2
#define S_  2048
#define D_  1024
#define H_  16
#define HD_ 64
#define NEG_INF (__int_as_float(0xff800000))
#define MASKV (-1e30f)
#define SW128(o) ((o) ^ (((o) >> 3) & 0x70))

// ---------------- static device scratch (allocation-free rule) ----------------
__device__ __nv_bfloat16 g_enc_h[(size_t)4096 * 1024];
__device__ __nv_bfloat16 g_enc_l[(size_t)4096 * 1024];
__device__ __nv_bfloat16 g_w_h[(size_t)2048 * 1024];
__device__ __nv_bfloat16 g_w_l[(size_t)2048 * 1024];
__device__ __nv_bfloat16 g_qh[(size_t)B_ * H_ * S_ * HD_];
__device__ __nv_bfloat16 g_ql[(size_t)B_ * H_ * S_ * HD_];
__device__ __nv_bfloat16 g_kh[(size_t)B_ * H_ * S_ * HD_];
__device__ __nv_bfloat16 g_kl[(size_t)B_ * H_ * S_ * HD_];
__device__ float g_m[B_ * H_ * S_];
__device__ float g_vinv[B_ * H_ * S_];

// ---------------- helpers (family-common ISA only: sm_80+) ----------------
__device__ __forceinline__ uint32_t smem_u32(const void* p) {
    uint32_t a;
    asm("{ .reg .u64 t; cvta.to.shared.u64 t, %1; cvt.u32.u64 %0, t; }" : "=r"(a) : "l"(p));
    return a;
}
#define CP_ASYNC16(dst, src) \
    asm volatile("cp.async.cg.shared.global [%0], [%1], 16;" :: "r"(dst), "l"(src))
#define CP_COMMIT() asm volatile("cp.async.commit_group;" ::: "memory")
#define CP_WAIT0()  asm volatile("cp.async.wait_group 0;" ::: "memory")

#define LDSM4(r, a)                                                            \
    asm volatile("ldmatrix.sync.aligned.m8n8.x4.shared.b16 {%0,%1,%2,%3}, [%4];" \
        : "=r"((r)[0]), "=r"((r)[1]), "=r"((r)[2]), "=r"((r)[3]) : "r"(a))

__device__ __forceinline__ void mma_bf16(float* c, const uint32_t* a, const uint32_t* b) {
    asm volatile(
        "mma.sync.aligned.m16n8k16.row.col.f32.bf16.bf16.f32 "
        "{%0,%1,%2,%3}, {%4,%5,%6,%7}, {%8,%9}, {%0,%1,%2,%3};"
        : "+f"(c[0]), "+f"(c[1]), "+f"(c[2]), "+f"(c[3])
        : "r"(a[0]), "r"(a[1]), "r"(a[2]), "r"(a[3]), "r"(b[0]), "r"(b[1]));
}

__device__ __forceinline__ void split2(float a, float b, __nv_bfloat162& h, __nv_bfloat162& l) {
    __nv_bfloat16 ha = __float2bfloat16_rn(a), hb = __float2bfloat16_rn(b);
    h.x = ha; h.y = hb;
    l.x = __float2bfloat16_rn(a - __bfloat162float(ha));
    l.y = __float2bfloat16_rn(b - __bfloat162float(hb));
}

// ---------------- split kernels: fp32 -> bf16 hi/lo ----------------
__global__ void split_enc(const float* __restrict__ x) {
    int i = blockIdx.x * 256 + threadIdx.x;
    float4 v = ((const float4*)x)[i];
    __nv_bfloat162 h01, l01, h23, l23;
    split2(v.x, v.y, h01, l01);
    split2(v.z, v.w, h23, l23);
    ((__nv_bfloat162*)g_enc_h)[2 * i]     = h01;
    ((__nv_bfloat162*)g_enc_h)[2 * i + 1] = h23;
    ((__nv_bfloat162*)g_enc_l)[2 * i]     = l01;
    ((__nv_bfloat162*)g_enc_l)[2 * i + 1] = l23;
}
__global__ void split_w(const float* __restrict__ x) {
    int i = blockIdx.x * 256 + threadIdx.x;
    float4 v = ((const float4*)x)[i];
    __nv_bfloat162 h01, l01, h23, l23;
    split2(v.x, v.y, h01, l01);
    split2(v.z, v.w, h23, l23);
    ((__nv_bfloat162*)g_w_h)[2 * i]     = h01;
    ((__nv_bfloat162*)g_w_h)[2 * i + 1] = h23;
    ((__nv_bfloat162*)g_w_l)[2 * i]     = l01;
    ((__nv_bfloat162*)g_w_l)[2 * i + 1] = l23;
}

// ---------------- projection GEMM: qk = enc @ W^T + bias ----------------
// smem: buf b at b*65536: Ah@0 Al@16384 Bh@32768 Bl@49152 ; tile = 128 rows x 64 bf16 (SW128)
#define PROJ_SMEM (2 * 65536)

__global__ __launch_bounds__(256, 1) void proj_mma(const float* __restrict__ bias) {
    extern __shared__ char smem[];
    const int tid = threadIdx.x, l = tid & 31, w = tid >> 5;
    const int e0 = blockIdx.x * 128, m0 = blockIdx.y * 128;
    const uint32_t sb = smem_u32(smem);
    const int wm = (w & 3) * 32, wn = (w >> 2) * 64;

    auto prefetch = [&](int buf, int k0) {
        #pragma unroll
        for (int i = 0; i < 16; i++) {
            int gi = tid + i * 256;
            int tl = gi >> 10, idx = gi & 1023, row = idx >> 3, c8 = idx & 7;
            const __nv_bfloat16* src;
            if      (tl == 0) src = g_enc_h + (size_t)(m0 + row) * D_ + k0 + c8 * 8;
            else if (tl == 1) src = g_enc_l + (size_t)(m0 + row) * D_ + k0 + c8 * 8;
            else if (tl == 2) src = g_w_h   + (size_t)(e0 + row) * D_ + k0 + c8 * 8;
            else              src = g_w_l   + (size_t)(e0 + row) * D_ + k0 + c8 * 8;
            CP_ASYNC16(sb + buf * 65536 + tl * 16384 + SW128(row * 128 + c8 * 16), src);
        }
    };

    prefetch(0, 0);
    CP_COMMIT();

    float acc[2][8][4];
    #pragma unroll
    for (int mt = 0; mt < 2; mt++)
        #pragma unroll
        for (int nt = 0; nt < 8; nt++)
            #pragma unroll
            for (int e = 0; e < 4; e++) acc[mt][nt][e] = 0.f;

    for (int j = 0; j < 16; j++) {
        CP_WAIT0();
        __syncthreads();
        if (j < 15) { prefetch((j + 1) & 1, (j + 1) * 64); CP_COMMIT(); }

        const uint32_t tb = sb + (j & 1) * 65536;
        #pragma unroll
        for (int s = 0; s < 4; s++) {
            const int acol = s * 32 + ((l >> 4) << 4);
            uint32_t ah[2][4], al[2][4];
            #pragma unroll
            for (int mt = 0; mt < 2; mt++) {
                const int arow = wm + mt * 16 + (l & 15);
                LDSM4(ah[mt], tb + SW128(arow * 128 + acol));
                LDSM4(al[mt], tb + 16384 + SW128(arow * 128 + acol));
            }
            #pragma unroll
            for (int tp = 0; tp < 4; tp++) {
                const int brow = wn + tp * 16 + (l & 7) + ((l >> 4) << 3);
                const int bcol = s * 32 + (((l >> 3) & 1) << 4);
                uint32_t bhf[4], blf[4];
                LDSM4(bhf, tb + 32768 + SW128(brow * 128 + bcol));
                LDSM4(blf, tb + 49152 + SW128(brow * 128 + bcol));
                #pragma unroll
                for (int mt = 0; mt < 2; mt++)
                    #pragma unroll
                    for (int nn = 0; nn < 2; nn++) {
                        float* c = acc[mt][2 * tp + nn];
                        mma_bf16(c, ah[mt], bhf + 2 * nn);
                        mma_bf16(c, ah[mt], blf + 2 * nn);
                        mma_bf16(c, al[mt], bhf + 2 * nn);
                    }
            }
        }
        __syncthreads();
    }

    // Epilogue: bias, fold 0.125 into q, split hi/lo, scatter [b][h][s][hd]
    #pragma unroll
    for (int mt = 0; mt < 2; mt++)
        #pragma unroll
        for (int nt = 0; nt < 8; nt++) {
            const int cp = e0 + wn + nt * 8 + 2 * (l & 3);
            const bool isq = (cp < D_);
            const int eh = isq ? cp : cp - D_;
            const int head = eh >> 6, hd0 = eh & 63;
            const float b0 = __ldg(bias + cp), b1 = __ldg(bias + cp + 1);
            const float scf = isq ? 0.125f : 1.0f;
            __nv_bfloat16* dh = isq ? g_qh : g_kh;
            __nv_bfloat16* dl = isq ? g_ql : g_kl;
            #pragma unroll
            for (int rh = 0; rh < 2; rh++) {
                const int m = m0 + wm + mt * 16 + (l >> 2) + rh * 8;
                const int bb = m >> 11, s = m & (S_ - 1);
                const size_t base = (((size_t)bb * H_ + head) * S_ + s) * HD_ + hd0;
                const float v0 = (acc[mt][nt][2 * rh]     + b0) * scf;
                const float v1 = (acc[mt][nt][2 * rh + 1] + b1) * scf;
                __nv_bfloat162 h2, l2;
                split2(v0, v1, h2, l2);
                *(__nv_bfloat162*)(dh + base) = h2;
                *(__nv_bfloat162*)(dl + base) = l2;
            }
        }
}

// ---------------- attention scores + causal softmax (two-pass) ----------------
// smem: Q hi@0 lo@16384 ; K buf b at 32768 + b*32768 (hi@0 lo@16384 within buf)
#define ATTN_SMEM (32768 + 2 * 32768)

template <int MODE>
__global__ __launch_bounds__(256, 1) void attn_mma(float* __restrict__ out) {
    extern __shared__ char smem[];
    const int tid = threadIdx.x, l = tid & 31, w = tid >> 5;
    const int bx = blockIdx.x, t0 = bx * 128;
    const int bh = blockIdx.z * H_ + blockIdx.y;
    const uint32_t sb = smem_u32(smem);

    const __nv_bfloat16* qh = g_qh + ((size_t)bh * S_ + t0) * HD_;
    const __nv_bfloat16* ql = g_ql + ((size_t)bh * S_ + t0) * HD_;
    const __nv_bfloat16* khb = g_kh + (size_t)bh * S_ * HD_;
    const __nv_bfloat16* klb = g_kl + (size_t)bh * S_ * HD_;

    auto prefetch_k = [&](int buf, int chunk) {
        const __nv_bfloat16* kh = khb + (size_t)chunk * 128 * HD_;
        const __nv_bfloat16* kl = klb + (size_t)chunk * 128 * HD_;
        #pragma unroll
        for (int i = 0; i < 8; i++) {
            int gi = tid + i * 256;
            int tl = gi >> 10, idx = gi & 1023, row = idx >> 3, c8 = idx & 7;
            CP_ASYNC16(sb + 32768 + buf * 32768 + tl * 16384 + SW128(row * 128 + c8 * 16),
                       (tl ? kl : kh) + row * HD_ + c8 * 8);
        }
    };

    // Q (persistent) + K chunk 0
    #pragma unroll
    for (int i = 0; i < 8; i++) {
        int gi = tid + i * 256;
        int tl = gi >> 10, idx = gi & 1023, row = idx >> 3, c8 = idx & 7;
        CP_ASYNC16(sb + tl * 16384 + SW128(row * 128 + c8 * 16),
                   (tl ? ql : qh) + row * HD_ + c8 * 8);
    }
    prefetch_k(0, 0);
    CP_COMMIT();

    const int r0 = 16 * w + (l >> 2), r1 = r0 + 8;   // local query rows
    float mrun0 = MASKV, mrun1 = MASKV, d0 = 0.f, d1 = 0.f;
    float mrow0 = 0.f, mrow1 = 0.f, vi0 = 0.f, vi1 = 0.f;
    if (MODE == 1) {
        mrow0 = g_m[bh * S_ + t0 + r0];   vi0 = g_vinv[bh * S_ + t0 + r0];
        mrow1 = g_m[bh * S_ + t0 + r1];   vi1 = g_vinv[bh * S_ + t0 + r1];
    }

    for (int j = 0; j <= bx; j++) {
        CP_WAIT0();
        __syncthreads();
        if (j < bx) { prefetch_k((j + 1) & 1, j + 1); CP_COMMIT(); }

        const uint32_t kb = sb + 32768 + (j & 1) * 32768;
        float acc[16][4];
        #pragma unroll
        for (int nt = 0; nt < 16; nt++)
            #pragma unroll
            for (int e = 0; e < 4; e++) acc[nt][e] = 0.f;

        #pragma unroll
        for (int s = 0; s < 4; s++) {
            const int arow = 16 * w + (l & 15);
            const int acol = s * 32 + ((l >> 4) << 4);
            uint32_t ah[4], al[4];
            LDSM4(ah, sb + SW128(arow * 128 + acol));
            LDSM4(al, sb + 16384 + SW128(arow * 128 + acol));
            #pragma unroll
            for (int tp = 0; tp < 8; tp++) {
                const int brow = tp * 16 + (l & 7) + ((l >> 4) << 3);
                const int bcol = s * 32 + (((l >> 3) & 1) << 4);
                uint32_t bhf[4], blf[4];
                LDSM4(bhf, kb + SW128(brow * 128 + bcol));
                LDSM4(blf, kb + 16384 + SW128(brow * 128 + bcol));
                #pragma unroll
                for (int nn = 0; nn < 2; nn++) {
                    float* c = acc[2 * tp + nn];
                    mma_bf16(c, ah, bhf + 2 * nn);
                    mma_bf16(c, ah, blf + 2 * nn);
                    mma_bf16(c, al, bhf + 2 * nn);
                }
            }
        }

        if (j == bx && MODE == 0) {  // finite mask value: no inf-inf NaNs in stats
            #pragma unroll
            for (int nt = 0; nt < 16; nt++)
                #pragma unroll
                for (int e = 0; e < 2; e++) {
                    const int cl = nt * 8 + 2 * (l & 3) + e;
                    if (cl > r0) acc[nt][e]     = MASKV;
                    if (cl > r1) acc[nt][2 + e] = MASKV;
                }
        }

        if (MODE == 0) {
            float mx0 = MASKV, mx1 = MASKV;
            #pragma unroll
            for (int nt = 0; nt < 16; nt++) {
                mx0 = fmaxf(mx0, fmaxf(acc[nt][0], acc[nt][1]));
                mx1 = fmaxf(mx1, fmaxf(acc[nt][2], acc[nt][3]));
            }
            const float mn0 = fmaxf(mrun0, mx0), mn1 = fmaxf(mrun1, mx1);
            float a0 = d0 * __expf(mrun0 - mn0);
            float a1 = d1 * __expf(mrun1 - mn1);
            #pragma unroll
            for (int nt = 0; nt < 16; nt++) {
                a0 += __expf(acc[nt][0] - mn0) + __expf(acc[nt][1] - mn0);
                a1 += __expf(acc[nt][2] - mn1) + __expf(acc[nt][3] - mn1);
            }
            d0 = a0; mrun0 = mn0;
            d1 = a1; mrun1 = mn1;
        } else {
            const bool diag = (j == bx);
            float* o0 = out + ((size_t)bh * S_ + t0 + r0) * S_ + j * 128 + 2 * (l & 3);
            float* o1 = out + ((size_t)bh * S_ + t0 + r1) * S_ + j * 128 + 2 * (l & 3);
            #pragma unroll
            for (int nt = 0; nt < 16; nt++) {
                const int cl = nt * 8 + 2 * (l & 3);
                float2 p0, p1;
                p0.x = (diag && cl     > r0) ? 0.f : __expf(acc[nt][0] - mrow0) * vi0;
                p0.y = (diag && cl + 1 > r0) ? 0.f : __expf(acc[nt][1] - mrow0) * vi0;
                p1.x = (diag && cl     > r1) ? 0.f : __expf(acc[nt][2] - mrow1) * vi1;
                p1.y = (diag && cl + 1 > r1) ? 0.f : __expf(acc[nt][3] - mrow1) * vi1;
                *(float2*)(o0 + nt * 8) = p0;
                *(float2*)(o1 + nt * 8) = p1;
            }
        }
    }

    if (MODE == 0) {
        // merge stats across the 4 lanes of each quad (same row); MASKV lanes
        // contribute d * exp(MASKV - mn) == 0 when any lane saw real data.
        #pragma unroll
        for (int off = 1; off <= 2; off <<= 1) {
            float mo0 = __shfl_xor_sync(0xffffffffu, mrun0, off);
            float do0 = __shfl_xor_sync(0xffffffffu, d0, off);
            float mo1 = __shfl_xor_sync(0xffffffffu, mrun1, off);
            float do1 = __shfl_xor_sync(0xffffffffu, d1, off);
            float mn0 = fmaxf(mrun0, mo0), mn1 = fmaxf(mrun1, mo1);
            d0 = d0 * __expf(mrun0 - mn0) + do0 * __expf(mo0 - mn0);
            d1 = d1 * __expf(mrun1 - mn1) + do1 * __expf(mo1 - mn1);
            mrun0 = mn0; mrun1 = mn1;
        }
        if ((l & 3) == 0) {
            g_m[bh * S_ + t0 + r0] = mrun0;  g_vinv[bh * S_ + t0 + r0] = 1.f / d0;
            g_m[bh * S_ + t0 + r1] = mrun1;  g_vinv[bh * S_ + t0 + r1] = 1.f / d1;
        }
    } else {
        // zero-fill strictly-future columns
        const int cbase = 128 * (bx + 1);
        const int len = S_ - cbase;
        if (len > 0) {
            const int half = tid >> 7, row = tid & 127;
            float4* p = (float4*)(out + ((size_t)bh * S_ + t0 + row) * S_ + cbase
                                  + half * (len >> 1));
            const int n4 = len >> 3;
            const float4 z = make_float4(0.f, 0.f, 0.f, 0.f);
            for (int i = 0; i < n4; i++) p[i] = z;
        }
    }
}

// ---------------------------------------------------------------------------
extern "C" void kernel_launch(void* const* d_in, const int* in_sizes, int n_in,
                              void* d_out, int out_size)
{
    (void)in_sizes; (void)n_in; (void)out_size;
    const float* encoded = (const float*)d_in[0];  // [2, 2048, 1024]
    const float* W       = (const float*)d_in[1];  // [2048, 1024]
    const float* bias    = (const float*)d_in[2];  // [2048]
    float* out = (float*)d_out;                    // [2, 16, 2048, 2048]

    cudaFuncSetAttribute(proj_mma,    cudaFuncAttributeMaxDynamicSharedMemorySize, PROJ_SMEM);
    cudaFuncSetAttribute(attn_mma<0>, cudaFuncAttributeMaxDynamicSharedMemorySize, ATTN_SMEM);
    cudaFuncSetAttribute(attn_mma<1>, cudaFuncAttributeMaxDynamicSharedMemorySize, ATTN_SMEM);

    split_enc<<<4096, 256>>>(encoded);
    split_w<<<2048, 256>>>(W);
    proj_mma<<<dim3(16, 32), 256, PROJ_SMEM>>>(bias);
    attn_mma<0><<<dim3(16, H_, B_), 256, ATTN_SMEM>>>(out);
    attn_mma<1><<<dim3(16, H_, B_), 256, ATTN_SMEM>>>(out);
}

// round 6
// speedup vs baseline: 2.8007x; 1.0806x over previous
#include <cuda_runtime.h>
#include <cuda_bf16.h>
#include <cstdint>
#include <cstddef>

#define B_  2
#define S_  2048
#define D_  1024
#define H_  16
#define HD_ 64
#define LOG2E 1.4426950408889634f
#define SW128(o) ((o) ^ (((o) >> 3) & 0x70))

// ---------------- static device scratch (allocation-free rule) ----------------
__device__ __nv_bfloat16 g_enc_h[(size_t)4096 * 1024];
__device__ __nv_bfloat16 g_enc_l[(size_t)4096 * 1024];
__device__ __nv_bfloat16 g_w_h[(size_t)2048 * 1024];
__device__ __nv_bfloat16 g_w_l[(size_t)2048 * 1024];
__device__ __nv_bfloat16 g_qh[(size_t)B_ * H_ * S_ * HD_];
__device__ __nv_bfloat16 g_ql[(size_t)B_ * H_ * S_ * HD_];
__device__ __nv_bfloat16 g_kh[(size_t)B_ * H_ * S_ * HD_];
__device__ __nv_bfloat16 g_kl[(size_t)B_ * H_ * S_ * HD_];

// ---------------- helpers (family-common ISA only: sm_80+) ----------------
__device__ __forceinline__ uint32_t smem_u32(const void* p) {
    uint32_t a;
    asm("{ .reg .u64 t; cvta.to.shared.u64 t, %1; cvt.u32.u64 %0, t; }" : "=f"(*(float*)&a) : "l"(p));
    return a;
}
// (NB: correct constraint below — re-declared properly)
__device__ __forceinline__ uint32_t smem_addr(const void* p) {
    uint32_t a;
    asm("{ .reg .u64 t; cvta.to.shared.u64 t, %1; cvt.u32.u64 %0, t; }" : "=r"(a) : "l"(p));
    return a;
}
#define CP_ASYNC16(dst, src) \
    asm volatile("cp.async.cg.shared.global [%0], [%1], 16;" :: "r"(dst), "l"(src))
#define CP_COMMIT() asm volatile("cp.async.commit_group;" ::: "memory")
#define CP_WAIT0()  asm volatile("cp.async.wait_group 0;" ::: "memory")

#define LDSM4(r, a)                                                            \
    asm volatile("ldmatrix.sync.aligned.m8n8.x4.shared.b16 {%0,%1,%2,%3}, [%4];" \
        : "=r"((r)[0]), "=r"((r)[1]), "=r"((r)[2]), "=r"((r)[3]) : "r"(a))

__device__ __forceinline__ void mma_bf16(float* c, const uint32_t* a, const uint32_t* b) {
    asm volatile(
        "mma.sync.aligned.m16n8k16.row.col.f32.bf16.bf16.f32 "
        "{%0,%1,%2,%3}, {%4,%5,%6,%7}, {%8,%9}, {%0,%1,%2,%3};"
        : "+f"(c[0]), "+f"(c[1]), "+f"(c[2]), "+f"(c[3])
        : "r"(a[0]), "r"(a[1]), "r"(a[2]), "r"(a[3]), "r"(b[0]), "r"(b[1]));
}

__device__ __forceinline__ float ex2(float x) {
    float y;
    asm("ex2.approx.ftz.f32 %0, %1;" : "=f"(y) : "f"(x));
    return y;
}

__device__ __forceinline__ void split2(float a, float b, __nv_bfloat162& h, __nv_bfloat162& l) {
    __nv_bfloat16 ha = __float2bfloat16_rn(a), hb = __float2bfloat16_rn(b);
    h.x = ha; h.y = hb;
    l.x = __float2bfloat16_rn(a - __bfloat162float(ha));
    l.y = __float2bfloat16_rn(b - __bfloat162float(hb));
}

// ---------------- split kernels: fp32 -> bf16 hi/lo ----------------
__global__ void split_enc(const float* __restrict__ x) {
    int i = blockIdx.x * 256 + threadIdx.x;
    float4 v = ((const float4*)x)[i];
    __nv_bfloat162 h01, l01, h23, l23;
    split2(v.x, v.y, h01, l01);
    split2(v.z, v.w, h23, l23);
    ((__nv_bfloat162*)g_enc_h)[2 * i]     = h01;
    ((__nv_bfloat162*)g_enc_h)[2 * i + 1] = h23;
    ((__nv_bfloat162*)g_enc_l)[2 * i]     = l01;
    ((__nv_bfloat162*)g_enc_l)[2 * i + 1] = l23;
}
__global__ void split_w(const float* __restrict__ x) {
    int i = blockIdx.x * 256 + threadIdx.x;
    float4 v = ((const float4*)x)[i];
    __nv_bfloat162 h01, l01, h23, l23;
    split2(v.x, v.y, h01, l01);
    split2(v.z, v.w, h23, l23);
    ((__nv_bfloat162*)g_w_h)[2 * i]     = h01;
    ((__nv_bfloat162*)g_w_h)[2 * i + 1] = h23;
    ((__nv_bfloat162*)g_w_l)[2 * i]     = l01;
    ((__nv_bfloat162*)g_w_l)[2 * i + 1] = l23;
}

// ---------------- projection GEMM: qk = enc @ W^T + bias ----------------
// smem: buf b at b*65536: Ah@0 Al@16384 Bh@32768 Bl@49152 ; tile = 128 rows x 64 bf16 (SW128)
#define PROJ_SMEM (2 * 65536)

__global__ __launch_bounds__(256, 1) void proj_mma(const float* __restrict__ bias) {
    extern __shared__ char smem[];
    const int tid = threadIdx.x, l = tid & 31, w = tid >> 5;
    const int e0 = blockIdx.x * 128, m0 = blockIdx.y * 128;
    const uint32_t sb = smem_addr(smem);
    const int wm = (w & 3) * 32, wn = (w >> 2) * 64;

    auto prefetch = [&](int buf, int k0) {
        #pragma unroll
        for (int i = 0; i < 16; i++) {
            int gi = tid + i * 256;
            int tl = gi >> 10, idx = gi & 1023, row = idx >> 3, c8 = idx & 7;
            const __nv_bfloat16* src;
            if      (tl == 0) src = g_enc_h + (size_t)(m0 + row) * D_ + k0 + c8 * 8;
            else if (tl == 1) src = g_enc_l + (size_t)(m0 + row) * D_ + k0 + c8 * 8;
            else if (tl == 2) src = g_w_h   + (size_t)(e0 + row) * D_ + k0 + c8 * 8;
            else              src = g_w_l   + (size_t)(e0 + row) * D_ + k0 + c8 * 8;
            CP_ASYNC16(sb + buf * 65536 + tl * 16384 + SW128(row * 128 + c8 * 16), src);
        }
    };

    prefetch(0, 0);
    CP_COMMIT();

    float acc[2][8][4];
    #pragma unroll
    for (int mt = 0; mt < 2; mt++)
        #pragma unroll
        for (int nt = 0; nt < 8; nt++)
            #pragma unroll
            for (int e = 0; e < 4; e++) acc[mt][nt][e] = 0.f;

    for (int j = 0; j < 16; j++) {
        CP_WAIT0();
        __syncthreads();
        if (j < 15) { prefetch((j + 1) & 1, (j + 1) * 64); CP_COMMIT(); }

        const uint32_t tb = sb + (j & 1) * 65536;
        #pragma unroll
        for (int s = 0; s < 4; s++) {
            const int acol = s * 32 + ((l >> 4) << 4);
            uint32_t ah[2][4], al[2][4];
            #pragma unroll
            for (int mt = 0; mt < 2; mt++) {
                const int arow = wm + mt * 16 + (l & 15);
                LDSM4(ah[mt], tb + SW128(arow * 128 + acol));
                LDSM4(al[mt], tb + 16384 + SW128(arow * 128 + acol));
            }
            #pragma unroll
            for (int tp = 0; tp < 4; tp++) {
                const int brow = wn + tp * 16 + (l & 7) + ((l >> 4) << 3);
                const int bcol = s * 32 + (((l >> 3) & 1) << 4);
                uint32_t bhf[4], blf[4];
                LDSM4(bhf, tb + 32768 + SW128(brow * 128 + bcol));
                LDSM4(blf, tb + 49152 + SW128(brow * 128 + bcol));
                #pragma unroll
                for (int mt = 0; mt < 2; mt++)
                    #pragma unroll
                    for (int nn = 0; nn < 2; nn++) {
                        float* c = acc[mt][2 * tp + nn];
                        mma_bf16(c, ah[mt], bhf + 2 * nn);
                        mma_bf16(c, ah[mt], blf + 2 * nn);
                        mma_bf16(c, al[mt], bhf + 2 * nn);
                    }
            }
        }
        __syncthreads();
    }

    // Epilogue: bias; q gets 0.125*log2(e) folded in (scores land in log2 domain)
    #pragma unroll
    for (int mt = 0; mt < 2; mt++)
        #pragma unroll
        for (int nt = 0; nt < 8; nt++) {
            const int cp = e0 + wn + nt * 8 + 2 * (l & 3);
            const bool isq = (cp < D_);
            const int eh = isq ? cp : cp - D_;
            const int head = eh >> 6, hd0 = eh & 63;
            const float b0 = __ldg(bias + cp), b1 = __ldg(bias + cp + 1);
            const float scf = isq ? (0.125f * LOG2E) : 1.0f;
            __nv_bfloat16* dh = isq ? g_qh : g_kh;
            __nv_bfloat16* dl = isq ? g_ql : g_kl;
            #pragma unroll
            for (int rh = 0; rh < 2; rh++) {
                const int m = m0 + wm + mt * 16 + (l >> 2) + rh * 8;
                const int bb = m >> 11, s = m & (S_ - 1);
                const size_t base = (((size_t)bb * H_ + head) * S_ + s) * HD_ + hd0;
                const float v0 = (acc[mt][nt][2 * rh]     + b0) * scf;
                const float v1 = (acc[mt][nt][2 * rh + 1] + b1) * scf;
                __nv_bfloat162 h2, l2;
                split2(v0, v1, h2, l2);
                *(__nv_bfloat162*)(dh + base) = h2;
                *(__nv_bfloat162*)(dl + base) = l2;
            }
        }
}

// ---------------- fused attention: stats pass + write pass in one kernel ----------------
// smem: Q hi@0 lo@16384 ; K buf b at 32768 + b*32768 (hi@0 lo@16384 within buf)
#define ATTN_SMEM (32768 + 2 * 32768)

// One half (64 key-cols) of a 128x128 score tile for this warp: acc[8][4]
__device__ __forceinline__ void mma_half(float (&acc)[8][4], uint32_t qb, uint32_t kb,
                                         int h, int l, int w) {
    #pragma unroll
    for (int nt = 0; nt < 8; nt++)
        #pragma unroll
        for (int e = 0; e < 4; e++) acc[nt][e] = 0.f;
    const int arow = 16 * w + (l & 15);
    #pragma unroll
    for (int s = 0; s < 4; s++) {
        const int acol = s * 32 + ((l >> 4) << 4);
        uint32_t ah[4], al[4];
        LDSM4(ah, qb + SW128(arow * 128 + acol));
        LDSM4(al, qb + 16384 + SW128(arow * 128 + acol));
        #pragma unroll
        for (int tpl = 0; tpl < 4; tpl++) {
            const int brow = (h * 4 + tpl) * 16 + (l & 7) + ((l >> 4) << 3);
            const int bcol = s * 32 + (((l >> 3) & 1) << 4);
            uint32_t bhf[4], blf[4];
            LDSM4(bhf, kb + SW128(brow * 128 + bcol));
            LDSM4(blf, kb + 16384 + SW128(brow * 128 + bcol));
            #pragma unroll
            for (int nn = 0; nn < 2; nn++) {
                float* c = acc[2 * tpl + nn];
                mma_bf16(c, ah, bhf + 2 * nn);
                mma_bf16(c, ah, blf + 2 * nn);
                mma_bf16(c, al, bhf + 2 * nn);
            }
        }
    }
}

__global__ __launch_bounds__(256, 2) void attn_fused(float* __restrict__ out) {
    extern __shared__ char smem[];
    const int tid = threadIdx.x, l = tid & 31, w = tid >> 5;
    const int bx = 15 - blockIdx.x;                // big tiles launch first
    const int t0 = bx * 128;
    const int bh = blockIdx.z * H_ + blockIdx.y;
    const uint32_t sb = smem_addr(smem);

    const __nv_bfloat16* qh = g_qh + ((size_t)bh * S_ + t0) * HD_;
    const __nv_bfloat16* ql = g_ql + ((size_t)bh * S_ + t0) * HD_;
    const __nv_bfloat16* khb = g_kh + (size_t)bh * S_ * HD_;
    const __nv_bfloat16* klb = g_kl + (size_t)bh * S_ * HD_;

    auto prefetch_k = [&](int buf, int chunk) {
        const __nv_bfloat16* kh = khb + (size_t)chunk * 128 * HD_;
        const __nv_bfloat16* kl = klb + (size_t)chunk * 128 * HD_;
        #pragma unroll
        for (int i = 0; i < 8; i++) {
            int gi = tid + i * 256;
            int tl = gi >> 10, idx = gi & 1023, row = idx >> 3, c8 = idx & 7;
            CP_ASYNC16(sb + 32768 + buf * 32768 + tl * 16384 + SW128(row * 128 + c8 * 16),
                       (tl ? kl : kh) + row * HD_ + c8 * 8);
        }
    };

    // Q (persistent) + K chunk 0
    #pragma unroll
    for (int i = 0; i < 8; i++) {
        int gi = tid + i * 256;
        int tl = gi >> 10, idx = gi & 1023, row = idx >> 3, c8 = idx & 7;
        CP_ASYNC16(sb + tl * 16384 + SW128(row * 128 + c8 * 16),
                   (tl ? ql : qh) + row * HD_ + c8 * 8);
    }
    prefetch_k(0, 0);
    CP_COMMIT();

    const int r0 = 16 * w + (l >> 2), r1 = r0 + 8;   // local query rows
    float d0 = 0.f, d1 = 0.f;                        // row sums of 2^score (no max shift)

    // ---- phase A: row sums ----
    for (int j = 0; j <= bx; j++) {
        CP_WAIT0();
        __syncthreads();
        if (j < bx) prefetch_k((j + 1) & 1, j + 1);
        else        prefetch_k((bx + 1) & 1, 0);     // phase-B chunk 0
        CP_COMMIT();

        const uint32_t kb = sb + 32768 + (j & 1) * 32768;
        const bool diag = (j == bx);
        #pragma unroll
        for (int h = 0; h < 2; h++) {
            float acc[8][4];
            mma_half(acc, sb, kb, h, l, w);
            #pragma unroll
            for (int nt = 0; nt < 8; nt++)
                #pragma unroll
                for (int e = 0; e < 2; e++) {
                    const int cl = (h * 8 + nt) * 8 + 2 * (l & 3) + e;
                    float e0 = ex2(acc[nt][e]);
                    float e1 = ex2(acc[nt][2 + e]);
                    if (diag) {
                        if (cl > r0) e0 = 0.f;
                        if (cl > r1) e1 = 0.f;
                    }
                    d0 += e0; d1 += e1;
                }
        }
    }

    // full row sum lives in the 4 lanes of each quad
    #pragma unroll
    for (int off = 1; off <= 2; off <<= 1) {
        d0 += __shfl_xor_sync(0xffffffffu, d0, off);
        d1 += __shfl_xor_sync(0xffffffffu, d1, off);
    }
    const float vi0 = 1.f / d0, vi1 = 1.f / d1;

    // ---- phase B: probabilities ----
    float* o0 = out + ((size_t)bh * S_ + t0 + r0) * S_ + 2 * (l & 3);
    float* o1 = out + ((size_t)bh * S_ + t0 + r1) * S_ + 2 * (l & 3);

    for (int j = 0; j <= bx; j++) {
        CP_WAIT0();
        __syncthreads();
        if (j < bx) { prefetch_k((bx + j) & 1, j + 1); CP_COMMIT(); }

        const uint32_t kb = sb + 32768 + ((bx + 1 + j) & 1) * 32768;
        const bool diag = (j == bx);
        #pragma unroll
        for (int h = 0; h < 2; h++) {
            float acc[8][4];
            mma_half(acc, sb, kb, h, l, w);
            #pragma unroll
            for (int nt = 0; nt < 8; nt++) {
                const int cb = (h * 8 + nt) * 8;
                const int cl = cb + 2 * (l & 3);
                float2 p0, p1;
                p0.x = ex2(acc[nt][0]) * vi0;
                p0.y = ex2(acc[nt][1]) * vi0;
                p1.x = ex2(acc[nt][2]) * vi1;
                p1.y = ex2(acc[nt][3]) * vi1;
                if (diag) {
                    if (cl     > r0) p0.x = 0.f;
                    if (cl + 1 > r0) p0.y = 0.f;
                    if (cl     > r1) p1.x = 0.f;
                    if (cl + 1 > r1) p1.y = 0.f;
                }
                __stcs((float2*)(o0 + j * 128 + cb), p0);
                __stcs((float2*)(o1 + j * 128 + cb), p1);
            }
        }
    }

    // zero-fill strictly-future columns
    const int cbase = 128 * (bx + 1);
    const int len = S_ - cbase;
    if (len > 0) {
        const int half = tid >> 7, row = tid & 127;
        float4* p = (float4*)(out + ((size_t)bh * S_ + t0 + row) * S_ + cbase
                              + half * (len >> 1));
        const int n4 = len >> 3;
        const float4 z = make_float4(0.f, 0.f, 0.f, 0.f);
        for (int i = 0; i < n4; i++) __stcs(p + i, z);
    }
}

// ---------------------------------------------------------------------------
extern "C" void kernel_launch(void* const* d_in, const int* in_sizes, int n_in,
                              void* d_out, int out_size)
{
    (void)in_sizes; (void)n_in; (void)out_size;
    const float* encoded = (const float*)d_in[0];  // [2, 2048, 1024]
    const float* W       = (const float*)d_in[1];  // [2048, 1024]
    const float* bias    = (const float*)d_in[2];  // [2048]
    float* out = (float*)d_out;                    // [2, 16, 2048, 2048]

    cudaFuncSetAttribute(proj_mma,   cudaFuncAttributeMaxDynamicSharedMemorySize, PROJ_SMEM);
    cudaFuncSetAttribute(attn_fused, cudaFuncAttributeMaxDynamicSharedMemorySize, ATTN_SMEM);

    split_enc<<<4096, 256>>>(encoded);
    split_w<<<2048, 256>>>(W);
    proj_mma<<<dim3(16, 32), 256, PROJ_SMEM>>>(bias);
    attn_fused<<<dim3(16, H_, B_), 256, ATTN_SMEM>>>(out);
}

// round 7
// speedup vs baseline: 2.8806x; 1.0286x over previous
#include <cuda_runtime.h>
#include <cuda_bf16.h>
#include <cstdint>
#include <cstddef>

#define B_  2
#define S_  2048
#define D_  1024
#define H_  16
#define HD_ 64
#define LOG2E 1.4426950408889634f
#define SW128(o) ((o) ^ (((o) >> 3) & 0x70))

// ---------------- static device scratch (allocation-free rule) ----------------
__device__ __nv_bfloat16 g_enc_h[(size_t)4096 * 1024];
__device__ __nv_bfloat16 g_enc_l[(size_t)4096 * 1024];
__device__ __nv_bfloat16 g_w_h[(size_t)2048 * 1024];
__device__ __nv_bfloat16 g_w_l[(size_t)2048 * 1024];
__device__ __nv_bfloat16 g_qh[(size_t)B_ * H_ * S_ * HD_];
__device__ __nv_bfloat16 g_ql[(size_t)B_ * H_ * S_ * HD_];
__device__ __nv_bfloat16 g_kh[(size_t)B_ * H_ * S_ * HD_];
__device__ __nv_bfloat16 g_kl[(size_t)B_ * H_ * S_ * HD_];

// ---------------- helpers (family-common ISA only: sm_80+) ----------------
__device__ __forceinline__ uint32_t smem_addr(const void* p) {
    uint32_t a;
    asm("{ .reg .u64 t; cvta.to.shared.u64 t, %1; cvt.u32.u64 %0, t; }" : "=r"(a) : "l"(p));
    return a;
}
#define CP_ASYNC16(dst, src) \
    asm volatile("cp.async.cg.shared.global [%0], [%1], 16;" :: "r"(dst), "l"(src))
#define CP_COMMIT() asm volatile("cp.async.commit_group;" ::: "memory")
#define CP_WAIT0()  asm volatile("cp.async.wait_group 0;" ::: "memory")

#define LDSM4(r, a)                                                            \
    asm volatile("ldmatrix.sync.aligned.m8n8.x4.shared.b16 {%0,%1,%2,%3}, [%4];" \
        : "=r"((r)[0]), "=r"((r)[1]), "=r"((r)[2]), "=r"((r)[3]) : "r"(a))

__device__ __forceinline__ void mma_bf16(float* c, const uint32_t* a, const uint32_t* b) {
    asm volatile(
        "mma.sync.aligned.m16n8k16.row.col.f32.bf16.bf16.f32 "
        "{%0,%1,%2,%3}, {%4,%5,%6,%7}, {%8,%9}, {%0,%1,%2,%3};"
        : "+f"(c[0]), "+f"(c[1]), "+f"(c[2]), "+f"(c[3])
        : "r"(a[0]), "r"(a[1]), "r"(a[2]), "r"(a[3]), "r"(b[0]), "r"(b[1]));
}

__device__ __forceinline__ float ex2(float x) {
    float y;
    asm("ex2.approx.ftz.f32 %0, %1;" : "=f"(y) : "f"(x));
    return y;
}

__device__ __forceinline__ void split2(float a, float b, __nv_bfloat162& h, __nv_bfloat162& l) {
    __nv_bfloat16 ha = __float2bfloat16_rn(a), hb = __float2bfloat16_rn(b);
    h.x = ha; h.y = hb;
    l.x = __float2bfloat16_rn(a - __bfloat162float(ha));
    l.y = __float2bfloat16_rn(b - __bfloat162float(hb));
}

// ---------------- split kernels: fp32 -> bf16 hi/lo ----------------
__global__ void split_enc(const float* __restrict__ x) {
    int i = blockIdx.x * 256 + threadIdx.x;
    float4 v = ((const float4*)x)[i];
    __nv_bfloat162 h01, l01, h23, l23;
    split2(v.x, v.y, h01, l01);
    split2(v.z, v.w, h23, l23);
    ((__nv_bfloat162*)g_enc_h)[2 * i]     = h01;
    ((__nv_bfloat162*)g_enc_h)[2 * i + 1] = h23;
    ((__nv_bfloat162*)g_enc_l)[2 * i]     = l01;
    ((__nv_bfloat162*)g_enc_l)[2 * i + 1] = l23;
}
__global__ void split_w(const float* __restrict__ x) {
    int i = blockIdx.x * 256 + threadIdx.x;
    float4 v = ((const float4*)x)[i];
    __nv_bfloat162 h01, l01, h23, l23;
    split2(v.x, v.y, h01, l01);
    split2(v.z, v.w, h23, l23);
    ((__nv_bfloat162*)g_w_h)[2 * i]     = h01;
    ((__nv_bfloat162*)g_w_h)[2 * i + 1] = h23;
    ((__nv_bfloat162*)g_w_l)[2 * i]     = l01;
    ((__nv_bfloat162*)g_w_l)[2 * i + 1] = l23;
}

// ---------------- projection GEMM: qk = enc @ W^T + bias ----------------
// smem: buf b at b*65536: Ah@0 Al@16384 Bh@32768 Bl@49152 ; tile = 128 rows x 64 bf16 (SW128)
#define PROJ_SMEM (2 * 65536)

__global__ __launch_bounds__(256, 1) void proj_mma(const float* __restrict__ bias) {
    extern __shared__ char smem[];
    const int tid = threadIdx.x, l = tid & 31, w = tid >> 5;
    const int e0 = blockIdx.x * 128, m0 = blockIdx.y * 128;
    const uint32_t sb = smem_addr(smem);
    const int wm = (w & 3) * 32, wn = (w >> 2) * 64;

    auto prefetch = [&](int buf, int k0) {
        #pragma unroll
        for (int i = 0; i < 16; i++) {
            int gi = tid + i * 256;
            int tl = gi >> 10, idx = gi & 1023, row = idx >> 3, c8 = idx & 7;
            const __nv_bfloat16* src;
            if      (tl == 0) src = g_enc_h + (size_t)(m0 + row) * D_ + k0 + c8 * 8;
            else if (tl == 1) src = g_enc_l + (size_t)(m0 + row) * D_ + k0 + c8 * 8;
            else if (tl == 2) src = g_w_h   + (size_t)(e0 + row) * D_ + k0 + c8 * 8;
            else              src = g_w_l   + (size_t)(e0 + row) * D_ + k0 + c8 * 8;
            CP_ASYNC16(sb + buf * 65536 + tl * 16384 + SW128(row * 128 + c8 * 16), src);
        }
    };

    prefetch(0, 0);
    CP_COMMIT();

    float acc[2][8][4];
    #pragma unroll
    for (int mt = 0; mt < 2; mt++)
        #pragma unroll
        for (int nt = 0; nt < 8; nt++)
            #pragma unroll
            for (int e = 0; e < 4; e++) acc[mt][nt][e] = 0.f;

    for (int j = 0; j < 16; j++) {
        CP_WAIT0();
        __syncthreads();
        if (j < 15) { prefetch((j + 1) & 1, (j + 1) * 64); CP_COMMIT(); }

        const uint32_t tb = sb + (j & 1) * 65536;
        #pragma unroll
        for (int s = 0; s < 4; s++) {
            const int acol = s * 32 + ((l >> 4) << 4);
            uint32_t ah[2][4], al[2][4];
            #pragma unroll
            for (int mt = 0; mt < 2; mt++) {
                const int arow = wm + mt * 16 + (l & 15);
                LDSM4(ah[mt], tb + SW128(arow * 128 + acol));
                LDSM4(al[mt], tb + 16384 + SW128(arow * 128 + acol));
            }
            #pragma unroll
            for (int tp = 0; tp < 4; tp++) {
                const int brow = wn + tp * 16 + (l & 7) + ((l >> 4) << 3);
                const int bcol = s * 32 + (((l >> 3) & 1) << 4);
                uint32_t bhf[4], blf[4];
                LDSM4(bhf, tb + 32768 + SW128(brow * 128 + bcol));
                LDSM4(blf, tb + 49152 + SW128(brow * 128 + bcol));
                #pragma unroll
                for (int mt = 0; mt < 2; mt++)
                    #pragma unroll
                    for (int nn = 0; nn < 2; nn++) {
                        float* c = acc[mt][2 * tp + nn];
                        mma_bf16(c, ah[mt], bhf + 2 * nn);
                        mma_bf16(c, ah[mt], blf + 2 * nn);
                        mma_bf16(c, al[mt], bhf + 2 * nn);
                    }
            }
        }
        __syncthreads();
    }

    // Epilogue: bias; q gets 0.125*log2(e) folded in (scores land in log2 domain)
    #pragma unroll
    for (int mt = 0; mt < 2; mt++)
        #pragma unroll
        for (int nt = 0; nt < 8; nt++) {
            const int cp = e0 + wn + nt * 8 + 2 * (l & 3);
            const bool isq = (cp < D_);
            const int eh = isq ? cp : cp - D_;
            const int head = eh >> 6, hd0 = eh & 63;
            const float b0 = __ldg(bias + cp), b1 = __ldg(bias + cp + 1);
            const float scf = isq ? (0.125f * LOG2E) : 1.0f;
            __nv_bfloat16* dh = isq ? g_qh : g_kh;
            __nv_bfloat16* dl = isq ? g_ql : g_kl;
            #pragma unroll
            for (int rh = 0; rh < 2; rh++) {
                const int m = m0 + wm + mt * 16 + (l >> 2) + rh * 8;
                const int bb = m >> 11, s = m & (S_ - 1);
                const size_t base = (((size_t)bb * H_ + head) * S_ + s) * HD_ + hd0;
                const float v0 = (acc[mt][nt][2 * rh]     + b0) * scf;
                const float v1 = (acc[mt][nt][2 * rh + 1] + b1) * scf;
                __nv_bfloat162 h2, l2;
                split2(v0, v1, h2, l2);
                *(__nv_bfloat162*)(dh + base) = h2;
                *(__nv_bfloat162*)(dl + base) = l2;
            }
        }
}

// ---------------- fused attention: 4 warps x 32 q-rows, 128x128 chunk tiles ----------------
// smem: Q hi@0 lo@16384 ; K buf b at 32768 + b*32768 (hi@0 lo@16384 within buf)
#define ATTN_SMEM (32768 + 2 * 32768)

// Full 128-col chunk tile for this warp's 32 rows: acc[mt][16 col-groups][4]
__device__ __forceinline__ void mma_chunk(float (&acc)[2][16][4], uint32_t qb, uint32_t kb,
                                          int l, int w) {
    #pragma unroll
    for (int mt = 0; mt < 2; mt++)
        #pragma unroll
        for (int nt = 0; nt < 16; nt++)
            #pragma unroll
            for (int e = 0; e < 4; e++) acc[mt][nt][e] = 0.f;

    #pragma unroll
    for (int s = 0; s < 4; s++) {
        const int acol = s * 32 + ((l >> 4) << 4);
        uint32_t ah[2][4], al[2][4];
        #pragma unroll
        for (int mt = 0; mt < 2; mt++) {
            const int arow = 32 * w + mt * 16 + (l & 15);
            LDSM4(ah[mt], qb + SW128(arow * 128 + acol));
            LDSM4(al[mt], qb + 16384 + SW128(arow * 128 + acol));
        }
        #pragma unroll
        for (int tp = 0; tp < 8; tp++) {
            const int brow = tp * 16 + (l & 7) + ((l >> 4) << 3);
            const int bcol = s * 32 + (((l >> 3) & 1) << 4);
            uint32_t bhf[4], blf[4];
            LDSM4(bhf, kb + SW128(brow * 128 + bcol));
            LDSM4(blf, kb + 16384 + SW128(brow * 128 + bcol));
            #pragma unroll
            for (int mt = 0; mt < 2; mt++)
                #pragma unroll
                for (int nn = 0; nn < 2; nn++) {
                    float* c = acc[mt][2 * tp + nn];
                    mma_bf16(c, ah[mt], bhf + 2 * nn);
                    mma_bf16(c, ah[mt], blf + 2 * nn);
                    mma_bf16(c, al[mt], bhf + 2 * nn);
                }
        }
    }
}

__global__ __launch_bounds__(128, 2) void attn_fused(float* __restrict__ out) {
    extern __shared__ char smem[];
    const int tid = threadIdx.x, l = tid & 31, w = tid >> 5;
    const int bx = 15 - blockIdx.x;                // big tiles launch first
    const int t0 = bx * 128;
    const int bh = blockIdx.z * H_ + blockIdx.y;
    const uint32_t sb = smem_addr(smem);

    const __nv_bfloat16* qh = g_qh + ((size_t)bh * S_ + t0) * HD_;
    const __nv_bfloat16* ql = g_ql + ((size_t)bh * S_ + t0) * HD_;
    const __nv_bfloat16* khb = g_kh + (size_t)bh * S_ * HD_;
    const __nv_bfloat16* klb = g_kl + (size_t)bh * S_ * HD_;

    auto prefetch_k = [&](int buf, int chunk) {
        const __nv_bfloat16* kh = khb + (size_t)chunk * 128 * HD_;
        const __nv_bfloat16* kl = klb + (size_t)chunk * 128 * HD_;
        #pragma unroll
        for (int i = 0; i < 16; i++) {
            int gi = tid + i * 128;
            int tl = gi >> 10, idx = gi & 1023, row = idx >> 3, c8 = idx & 7;
            CP_ASYNC16(sb + 32768 + buf * 32768 + tl * 16384 + SW128(row * 128 + c8 * 16),
                       (tl ? kl : kh) + row * HD_ + c8 * 8);
        }
    };

    // Q (persistent) + K chunk 0
    #pragma unroll
    for (int i = 0; i < 16; i++) {
        int gi = tid + i * 128;
        int tl = gi >> 10, idx = gi & 1023, row = idx >> 3, c8 = idx & 7;
        CP_ASYNC16(sb + tl * 16384 + SW128(row * 128 + c8 * 16),
                   (tl ? ql : qh) + row * HD_ + c8 * 8);
    }
    prefetch_k(0, 0);
    CP_COMMIT();

    const int rq = (l >> 2);                       // quad row within 8
    float d[2][2] = {{0.f, 0.f}, {0.f, 0.f}};      // [mt][rowhalf] sums of 2^score

    // ---- phase A: row sums ----
    for (int j = 0; j <= bx; j++) {
        CP_WAIT0();
        __syncthreads();
        if (j < bx) prefetch_k((j + 1) & 1, j + 1);
        else        prefetch_k((bx + 1) & 1, 0);   // phase-B chunk 0
        CP_COMMIT();

        const uint32_t kb = sb + 32768 + (j & 1) * 32768;
        float acc[2][16][4];
        mma_chunk(acc, sb, kb, l, w);

        const bool diag = (j == bx);
        #pragma unroll
        for (int mt = 0; mt < 2; mt++) {
            const int rr0 = 32 * w + 16 * mt + rq, rr1 = rr0 + 8;
            #pragma unroll
            for (int nt = 0; nt < 16; nt++)
                #pragma unroll
                for (int e = 0; e < 2; e++) {
                    const int cl = nt * 8 + 2 * (l & 3) + e;
                    float e0 = ex2(acc[mt][nt][e]);
                    float e1 = ex2(acc[mt][nt][2 + e]);
                    if (diag) {
                        if (cl > rr0) e0 = 0.f;
                        if (cl > rr1) e1 = 0.f;
                    }
                    d[mt][0] += e0; d[mt][1] += e1;
                }
        }
    }

    // full row sum lives in the 4 lanes of each quad
    #pragma unroll
    for (int off = 1; off <= 2; off <<= 1) {
        #pragma unroll
        for (int mt = 0; mt < 2; mt++) {
            d[mt][0] += __shfl_xor_sync(0xffffffffu, d[mt][0], off);
            d[mt][1] += __shfl_xor_sync(0xffffffffu, d[mt][1], off);
        }
    }
    float vi[2][2];
    #pragma unroll
    for (int mt = 0; mt < 2; mt++) {
        vi[mt][0] = 1.f / d[mt][0];
        vi[mt][1] = 1.f / d[mt][1];
    }

    // ---- phase B: probabilities ----
    for (int j = 0; j <= bx; j++) {
        CP_WAIT0();
        __syncthreads();
        if (j < bx) { prefetch_k((bx + j) & 1, j + 1); CP_COMMIT(); }

        const uint32_t kb = sb + 32768 + ((bx + 1 + j) & 1) * 32768;
        float acc[2][16][4];
        mma_chunk(acc, sb, kb, l, w);

        const bool diag = (j == bx);
        #pragma unroll
        for (int mt = 0; mt < 2; mt++) {
            const int rr0 = 32 * w + 16 * mt + rq, rr1 = rr0 + 8;
            float* o0 = out + ((size_t)bh * S_ + t0 + rr0) * S_ + j * 128 + 2 * (l & 3);
            float* o1 = out + ((size_t)bh * S_ + t0 + rr1) * S_ + j * 128 + 2 * (l & 3);
            #pragma unroll
            for (int nt = 0; nt < 16; nt++) {
                const int cl = nt * 8 + 2 * (l & 3);
                float2 p0, p1;
                p0.x = ex2(acc[mt][nt][0]) * vi[mt][0];
                p0.y = ex2(acc[mt][nt][1]) * vi[mt][0];
                p1.x = ex2(acc[mt][nt][2]) * vi[mt][1];
                p1.y = ex2(acc[mt][nt][3]) * vi[mt][1];
                if (diag) {
                    if (cl     > rr0) p0.x = 0.f;
                    if (cl + 1 > rr0) p0.y = 0.f;
                    if (cl     > rr1) p1.x = 0.f;
                    if (cl + 1 > rr1) p1.y = 0.f;
                }
                __stcs((float2*)(o0 + nt * 8), p0);
                __stcs((float2*)(o1 + nt * 8), p1);
            }
        }
    }

    // zero-fill strictly-future columns (one row per thread)
    const int cbase = 128 * (bx + 1);
    const int len = S_ - cbase;
    if (len > 0) {
        float4* p = (float4*)(out + ((size_t)bh * S_ + t0 + tid) * S_ + cbase);
        const int n4 = len >> 2;
        const float4 z = make_float4(0.f, 0.f, 0.f, 0.f);
        for (int i = 0; i < n4; i++) __stcs(p + i, z);
    }
}

// ---------------------------------------------------------------------------
extern "C" void kernel_launch(void* const* d_in, const int* in_sizes, int n_in,
                              void* d_out, int out_size)
{
    (void)in_sizes; (void)n_in; (void)out_size;
    const float* encoded = (const float*)d_in[0];  // [2, 2048, 1024]
    const float* W       = (const float*)d_in[1];  // [2048, 1024]
    const float* bias    = (const float*)d_in[2];  // [2048]
    float* out = (float*)d_out;                    // [2, 16, 2048, 2048]

    cudaFuncSetAttribute(proj_mma,   cudaFuncAttributeMaxDynamicSharedMemorySize, PROJ_SMEM);
    cudaFuncSetAttribute(attn_fused, cudaFuncAttributeMaxDynamicSharedMemorySize, ATTN_SMEM);

    split_enc<<<4096, 256>>>(encoded);
    split_w<<<2048, 256>>>(W);
    proj_mma<<<dim3(16, 32), 256, PROJ_SMEM>>>(bias);
    attn_fused<<<dim3(16, H_, B_), 128, ATTN_SMEM>>>(out);
}

// round 8
// speedup vs baseline: 3.0456x; 1.0573x over previous
#include <cuda_runtime.h>
#include <cuda_bf16.h>
#include <cstdint>
#include <cstddef>

#define B_  2
#define S_  2048
#define D_  1024
#define H_  16
#define HD_ 64
#define LOG2E 1.4426950408889634f
#define SW128(o) ((o) ^ (((o) >> 3) & 0x70))

// ---------------- static device scratch (allocation-free rule) ----------------
__device__ __nv_bfloat16 g_enc_h[(size_t)4096 * 1024];
__device__ __nv_bfloat16 g_enc_l[(size_t)4096 * 1024];
__device__ __nv_bfloat16 g_w_h[(size_t)2048 * 1024];
__device__ __nv_bfloat16 g_w_l[(size_t)2048 * 1024];
__device__ __nv_bfloat16 g_qh[(size_t)B_ * H_ * S_ * HD_];
__device__ __nv_bfloat16 g_ql[(size_t)B_ * H_ * S_ * HD_];
__device__ __nv_bfloat16 g_kh[(size_t)B_ * H_ * S_ * HD_];
__device__ __nv_bfloat16 g_kl[(size_t)B_ * H_ * S_ * HD_];

// ---------------- helpers (family-common ISA only: sm_80+) ----------------
__device__ __forceinline__ uint32_t smem_addr(const void* p) {
    uint32_t a;
    asm("{ .reg .u64 t; cvta.to.shared.u64 t, %1; cvt.u32.u64 %0, t; }" : "=r"(a) : "l"(p));
    return a;
}
#define CP_ASYNC16(dst, src) \
    asm volatile("cp.async.cg.shared.global [%0], [%1], 16;" :: "r"(dst), "l"(src))
#define CP_COMMIT() asm volatile("cp.async.commit_group;" ::: "memory")
#define CP_WAIT0()  asm volatile("cp.async.wait_group 0;" ::: "memory")

#define LDSM4(r, a)                                                            \
    asm volatile("ldmatrix.sync.aligned.m8n8.x4.shared.b16 {%0,%1,%2,%3}, [%4];" \
        : "=r"((r)[0]), "=r"((r)[1]), "=r"((r)[2]), "=r"((r)[3]) : "r"(a))

__device__ __forceinline__ void mma_bf16(float* c, const uint32_t* a, const uint32_t* b) {
    asm volatile(
        "mma.sync.aligned.m16n8k16.row.col.f32.bf16.bf16.f32 "
        "{%0,%1,%2,%3}, {%4,%5,%6,%7}, {%8,%9}, {%0,%1,%2,%3};"
        : "+f"(c[0]), "+f"(c[1]), "+f"(c[2]), "+f"(c[3])
        : "r"(a[0]), "r"(a[1]), "r"(a[2]), "r"(a[3]), "r"(b[0]), "r"(b[1]));
}

__device__ __forceinline__ float ex2(float x) {
    float y;
    asm("ex2.approx.ftz.f32 %0, %1;" : "=f"(y) : "f"(x));
    return y;
}

__device__ __forceinline__ void split2(float a, float b, __nv_bfloat162& h, __nv_bfloat162& l) {
    __nv_bfloat16 ha = __float2bfloat16_rn(a), hb = __float2bfloat16_rn(b);
    h.x = ha; h.y = hb;
    l.x = __float2bfloat16_rn(a - __bfloat162float(ha));
    l.y = __float2bfloat16_rn(b - __bfloat162float(hb));
}

// ---------------- split kernel: fp32 -> bf16 hi/lo (enc + W in one launch) ----------------
__global__ void split_all(const float* __restrict__ enc, const float* __restrict__ Wm) {
    const int bx = blockIdx.x;
    if (bx < 4096) {
        int i = bx * 256 + threadIdx.x;
        float4 v = ((const float4*)enc)[i];
        __nv_bfloat162 h01, l01, h23, l23;
        split2(v.x, v.y, h01, l01);
        split2(v.z, v.w, h23, l23);
        ((__nv_bfloat162*)g_enc_h)[2 * i]     = h01;
        ((__nv_bfloat162*)g_enc_h)[2 * i + 1] = h23;
        ((__nv_bfloat162*)g_enc_l)[2 * i]     = l01;
        ((__nv_bfloat162*)g_enc_l)[2 * i + 1] = l23;
    } else {
        int i = (bx - 4096) * 256 + threadIdx.x;
        float4 v = ((const float4*)Wm)[i];
        __nv_bfloat162 h01, l01, h23, l23;
        split2(v.x, v.y, h01, l01);
        split2(v.z, v.w, h23, l23);
        ((__nv_bfloat162*)g_w_h)[2 * i]     = h01;
        ((__nv_bfloat162*)g_w_h)[2 * i + 1] = h23;
        ((__nv_bfloat162*)g_w_l)[2 * i]     = l01;
        ((__nv_bfloat162*)g_w_l)[2 * i + 1] = l23;
    }
}

// ---------------- projection GEMM: qk = enc @ W^T + bias ----------------
// smem: buf b at b*65536: Ah@0 Al@16384 Bh@32768 Bl@49152 ; tile = 128 rows x 64 bf16 (SW128)
#define PROJ_SMEM (2 * 65536)

__global__ __launch_bounds__(256, 1) void proj_mma(const float* __restrict__ bias) {
    extern __shared__ char smem[];
    const int tid = threadIdx.x, l = tid & 31, w = tid >> 5;
    const int e0 = blockIdx.x * 128, m0 = blockIdx.y * 128;
    const uint32_t sb = smem_addr(smem);
    const int wm = (w & 3) * 32, wn = (w >> 2) * 64;

    auto prefetch = [&](int buf, int k0) {
        #pragma unroll
        for (int i = 0; i < 16; i++) {
            int gi = tid + i * 256;
            int tl = gi >> 10, idx = gi & 1023, row = idx >> 3, c8 = idx & 7;
            const __nv_bfloat16* src;
            if      (tl == 0) src = g_enc_h + (size_t)(m0 + row) * D_ + k0 + c8 * 8;
            else if (tl == 1) src = g_enc_l + (size_t)(m0 + row) * D_ + k0 + c8 * 8;
            else if (tl == 2) src = g_w_h   + (size_t)(e0 + row) * D_ + k0 + c8 * 8;
            else              src = g_w_l   + (size_t)(e0 + row) * D_ + k0 + c8 * 8;
            CP_ASYNC16(sb + buf * 65536 + tl * 16384 + SW128(row * 128 + c8 * 16), src);
        }
    };

    prefetch(0, 0);
    CP_COMMIT();

    float acc[2][8][4];
    #pragma unroll
    for (int mt = 0; mt < 2; mt++)
        #pragma unroll
        for (int nt = 0; nt < 8; nt++)
            #pragma unroll
            for (int e = 0; e < 4; e++) acc[mt][nt][e] = 0.f;

    for (int j = 0; j < 16; j++) {
        CP_WAIT0();
        __syncthreads();
        if (j < 15) { prefetch((j + 1) & 1, (j + 1) * 64); CP_COMMIT(); }

        const uint32_t tb = sb + (j & 1) * 65536;
        #pragma unroll
        for (int s = 0; s < 4; s++) {
            const int acol = s * 32 + ((l >> 4) << 4);
            uint32_t ah[2][4], al[2][4];
            #pragma unroll
            for (int mt = 0; mt < 2; mt++) {
                const int arow = wm + mt * 16 + (l & 15);
                LDSM4(ah[mt], tb + SW128(arow * 128 + acol));
                LDSM4(al[mt], tb + 16384 + SW128(arow * 128 + acol));
            }
            #pragma unroll
            for (int tp = 0; tp < 4; tp++) {
                const int brow = wn + tp * 16 + (l & 7) + ((l >> 4) << 3);
                const int bcol = s * 32 + (((l >> 3) & 1) << 4);
                uint32_t bhf[4], blf[4];
                LDSM4(bhf, tb + 32768 + SW128(brow * 128 + bcol));
                LDSM4(blf, tb + 49152 + SW128(brow * 128 + bcol));
                #pragma unroll
                for (int mt = 0; mt < 2; mt++)
                    #pragma unroll
                    for (int nn = 0; nn < 2; nn++) {
                        float* c = acc[mt][2 * tp + nn];
                        mma_bf16(c, ah[mt], bhf + 2 * nn);
                        mma_bf16(c, ah[mt], blf + 2 * nn);
                        mma_bf16(c, al[mt], bhf + 2 * nn);
                    }
            }
        }
        __syncthreads();
    }

    // Epilogue: bias; q gets 0.125*log2(e) folded in (scores land in log2 domain)
    #pragma unroll
    for (int mt = 0; mt < 2; mt++)
        #pragma unroll
        for (int nt = 0; nt < 8; nt++) {
            const int cp = e0 + wn + nt * 8 + 2 * (l & 3);
            const bool isq = (cp < D_);
            const int eh = isq ? cp : cp - D_;
            const int head = eh >> 6, hd0 = eh & 63;
            const float b0 = __ldg(bias + cp), b1 = __ldg(bias + cp + 1);
            const float scf = isq ? (0.125f * LOG2E) : 1.0f;
            __nv_bfloat16* dh = isq ? g_qh : g_kh;
            __nv_bfloat16* dl = isq ? g_ql : g_kl;
            #pragma unroll
            for (int rh = 0; rh < 2; rh++) {
                const int m = m0 + wm + mt * 16 + (l >> 2) + rh * 8;
                const int bb = m >> 11, s = m & (S_ - 1);
                const size_t base = (((size_t)bb * H_ + head) * S_ + s) * HD_ + hd0;
                const float v0 = (acc[mt][nt][2 * rh]     + b0) * scf;
                const float v1 = (acc[mt][nt][2 * rh + 1] + b1) * scf;
                __nv_bfloat162 h2, l2;
                split2(v0, v1, h2, l2);
                *(__nv_bfloat162*)(dh + base) = h2;
                *(__nv_bfloat162*)(dl + base) = l2;
            }
        }
}

// ---------------- fused attention: 4 warps x 32 q-rows, 64-row K chunks ----------------
// smem: Q hi@0 lo@16384 ; K buf b at 32768 + b*16384 (hi@0 lo@8192 within buf)
// 64KB/block -> 3 blocks/SM; acc 64 regs -> no spills.
#define ATTN_SMEM (32768 + 2 * 16384)

// 32 q-rows x 64 k-rows chunk tile for this warp: acc[mt][8 col-groups][4]
__device__ __forceinline__ void mma_chunk64(float (&acc)[2][8][4], uint32_t qb, uint32_t kb,
                                            int l, int w) {
    #pragma unroll
    for (int mt = 0; mt < 2; mt++)
        #pragma unroll
        for (int nt = 0; nt < 8; nt++)
            #pragma unroll
            for (int e = 0; e < 4; e++) acc[mt][nt][e] = 0.f;

    #pragma unroll
    for (int s = 0; s < 4; s++) {
        const int acol = s * 32 + ((l >> 4) << 4);
        uint32_t ah[2][4], al[2][4];
        #pragma unroll
        for (int mt = 0; mt < 2; mt++) {
            const int arow = 32 * w + mt * 16 + (l & 15);
            LDSM4(ah[mt], qb + SW128(arow * 128 + acol));
            LDSM4(al[mt], qb + 16384 + SW128(arow * 128 + acol));
        }
        #pragma unroll
        for (int tp = 0; tp < 4; tp++) {
            const int brow = tp * 16 + (l & 7) + ((l >> 4) << 3);
            const int bcol = s * 32 + (((l >> 3) & 1) << 4);
            uint32_t bhf[4], blf[4];
            LDSM4(bhf, kb + SW128(brow * 128 + bcol));
            LDSM4(blf, kb + 8192 + SW128(brow * 128 + bcol));
            #pragma unroll
            for (int mt = 0; mt < 2; mt++)
                #pragma unroll
                for (int nn = 0; nn < 2; nn++) {
                    float* c = acc[mt][2 * tp + nn];
                    mma_bf16(c, ah[mt], bhf + 2 * nn);
                    mma_bf16(c, ah[mt], blf + 2 * nn);
                    mma_bf16(c, al[mt], bhf + 2 * nn);
                }
        }
    }
}

__global__ __launch_bounds__(128, 3) void attn_fused(float* __restrict__ out) {
    extern __shared__ char smem[];
    const int tid = threadIdx.x, l = tid & 31, w = tid >> 5;
    const int bx = 15 - blockIdx.x;                // big tiles launch first
    const int t0 = bx * 128;
    const int bh = blockIdx.z * H_ + blockIdx.y;
    const uint32_t sb = smem_addr(smem);

    const __nv_bfloat16* qh = g_qh + ((size_t)bh * S_ + t0) * HD_;
    const __nv_bfloat16* ql = g_ql + ((size_t)bh * S_ + t0) * HD_;
    const __nv_bfloat16* khb = g_kh + (size_t)bh * S_ * HD_;
    const __nv_bfloat16* klb = g_kl + (size_t)bh * S_ * HD_;

    auto prefetch_k = [&](int buf, int chunk) {      // 64-row chunk: 16KB
        const __nv_bfloat16* kh = khb + (size_t)chunk * 64 * HD_;
        const __nv_bfloat16* kl = klb + (size_t)chunk * 64 * HD_;
        #pragma unroll
        for (int i = 0; i < 8; i++) {
            int gi = tid + i * 128;
            int tl = gi >> 9, idx = gi & 511, row = idx >> 3, c8 = idx & 7;
            CP_ASYNC16(sb + 32768 + buf * 16384 + tl * 8192 + SW128(row * 128 + c8 * 16),
                       (tl ? kl : kh) + row * HD_ + c8 * 8);
        }
    };

    // Q (persistent, 32KB) + K chunk 0
    #pragma unroll
    for (int i = 0; i < 16; i++) {
        int gi = tid + i * 128;
        int tl = gi >> 10, idx = gi & 1023, row = idx >> 3, c8 = idx & 7;
        CP_ASYNC16(sb + tl * 16384 + SW128(row * 128 + c8 * 16),
                   (tl ? ql : qh) + row * HD_ + c8 * 8);
    }
    prefetch_k(0, 0);
    CP_COMMIT();

    const int rq = (l >> 2);                       // quad row within 8
    const int nj = 2 * bx + 2;                     // causal 64-col chunks
    float d[2][2] = {{0.f, 0.f}, {0.f, 0.f}};      // [mt][rowhalf] sums of 2^score

    // ---- phase A: row sums ----
    for (int j = 0; j < nj; j++) {
        CP_WAIT0();
        __syncthreads();
        prefetch_k((j + 1) & 1, (j + 1 < nj) ? j + 1 : 0);   // wraps to phase-B chunk 0
        CP_COMMIT();

        const uint32_t kb = sb + 32768 + (j & 1) * 16384;
        float acc[2][8][4];
        mma_chunk64(acc, sb, kb, l, w);

        const bool diag = (j >= 2 * bx);
        const int coff = (j - 2 * bx) * 64;        // column offset vs local rows (valid if diag)
        #pragma unroll
        for (int mt = 0; mt < 2; mt++) {
            const int rr0 = 32 * w + 16 * mt + rq, rr1 = rr0 + 8;
            #pragma unroll
            for (int nt = 0; nt < 8; nt++)
                #pragma unroll
                for (int e = 0; e < 2; e++) {
                    const int cl = nt * 8 + 2 * (l & 3) + e;
                    float e0 = ex2(acc[mt][nt][e]);
                    float e1 = ex2(acc[mt][nt][2 + e]);
                    if (diag) {
                        if (coff + cl > rr0) e0 = 0.f;
                        if (coff + cl > rr1) e1 = 0.f;
                    }
                    d[mt][0] += e0; d[mt][1] += e1;
                }
        }
    }

    // full row sum lives in the 4 lanes of each quad
    #pragma unroll
    for (int off = 1; off <= 2; off <<= 1) {
        #pragma unroll
        for (int mt = 0; mt < 2; mt++) {
            d[mt][0] += __shfl_xor_sync(0xffffffffu, d[mt][0], off);
            d[mt][1] += __shfl_xor_sync(0xffffffffu, d[mt][1], off);
        }
    }
    float vi[2][2];
    #pragma unroll
    for (int mt = 0; mt < 2; mt++) {
        vi[mt][0] = 1.f / d[mt][0];
        vi[mt][1] = 1.f / d[mt][1];
    }

    // ---- phase B: probabilities ----
    for (int j = 0; j < nj; j++) {
        CP_WAIT0();
        __syncthreads();
        if (j + 1 < nj) { prefetch_k((nj + j + 1) & 1, j + 1); CP_COMMIT(); }

        const uint32_t kb = sb + 32768 + ((nj + j) & 1) * 16384;
        float acc[2][8][4];
        mma_chunk64(acc, sb, kb, l, w);

        const bool diag = (j >= 2 * bx);
        const int coff = (j - 2 * bx) * 64;
        #pragma unroll
        for (int mt = 0; mt < 2; mt++) {
            const int rr0 = 32 * w + 16 * mt + rq, rr1 = rr0 + 8;
            float* o0 = out + ((size_t)bh * S_ + t0 + rr0) * S_ + j * 64 + 2 * (l & 3);
            float* o1 = out + ((size_t)bh * S_ + t0 + rr1) * S_ + j * 64 + 2 * (l & 3);
            #pragma unroll
            for (int nt = 0; nt < 8; nt++) {
                const int cl = nt * 8 + 2 * (l & 3);
                float2 p0, p1;
                p0.x = ex2(acc[mt][nt][0]) * vi[mt][0];
                p0.y = ex2(acc[mt][nt][1]) * vi[mt][0];
                p1.x = ex2(acc[mt][nt][2]) * vi[mt][1];
                p1.y = ex2(acc[mt][nt][3]) * vi[mt][1];
                if (diag) {
                    if (coff + cl     > rr0) p0.x = 0.f;
                    if (coff + cl + 1 > rr0) p0.y = 0.f;
                    if (coff + cl     > rr1) p1.x = 0.f;
                    if (coff + cl + 1 > rr1) p1.y = 0.f;
                }
                __stcs((float2*)(o0 + nt * 8), p0);
                __stcs((float2*)(o1 + nt * 8), p1);
            }
        }
    }

    // zero-fill strictly-future columns (one row per thread)
    const int cbase = 64 * nj;                     // == 128*(bx+1)
    const int len = S_ - cbase;
    if (len > 0) {
        float4* p = (float4*)(out + ((size_t)bh * S_ + t0 + tid) * S_ + cbase);
        const int n4 = len >> 2;
        const float4 z = make_float4(0.f, 0.f, 0.f, 0.f);
        for (int i = 0; i < n4; i++) __stcs(p + i, z);
    }
}

// ---------------------------------------------------------------------------
extern "C" void kernel_launch(void* const* d_in, const int* in_sizes, int n_in,
                              void* d_out, int out_size)
{
    (void)in_sizes; (void)n_in; (void)out_size;
    const float* encoded = (const float*)d_in[0];  // [2, 2048, 1024]
    const float* W       = (const float*)d_in[1];  // [2048, 1024]
    const float* bias    = (const float*)d_in[2];  // [2048]
    float* out = (float*)d_out;                    // [2, 16, 2048, 2048]

    cudaFuncSetAttribute(proj_mma,   cudaFuncAttributeMaxDynamicSharedMemorySize, PROJ_SMEM);
    cudaFuncSetAttribute(attn_fused, cudaFuncAttributeMaxDynamicSharedMemorySize, ATTN_SMEM);

    split_all<<<6144, 256>>>(encoded, W);
    proj_mma<<<dim3(16, 32), 256, PROJ_SMEM>>>(bias);
    attn_fused<<<dim3(16, H_, B_), 128, ATTN_SMEM>>>(out);
}

// round 9
// speedup vs baseline: 3.2360x; 1.0625x over previous
#include <cuda_runtime.h>
#include <cuda_bf16.h>
#include <cstdint>
#include <cstddef>

#define B_  2
#define S_  2048
#define D_  1024
#define H_  16
#define HD_ 64
#define LOG2E 1.4426950408889634f
#define SW128(o) ((o) ^ (((o) >> 3) & 0x70))

// ---------------- static device scratch (allocation-free rule) ----------------
__device__ __nv_bfloat16 g_enc_h[(size_t)4096 * 1024];
__device__ __nv_bfloat16 g_enc_l[(size_t)4096 * 1024];
__device__ __nv_bfloat16 g_w_h[(size_t)2048 * 1024];
__device__ __nv_bfloat16 g_w_l[(size_t)2048 * 1024];
__device__ __nv_bfloat16 g_qh[(size_t)B_ * H_ * S_ * HD_];
__device__ __nv_bfloat16 g_ql[(size_t)B_ * H_ * S_ * HD_];
__device__ __nv_bfloat16 g_kh[(size_t)B_ * H_ * S_ * HD_];
__device__ __nv_bfloat16 g_kl[(size_t)B_ * H_ * S_ * HD_];

// ---------------- helpers (family-common ISA only: sm_80+) ----------------
__device__ __forceinline__ uint32_t smem_addr(const void* p) {
    uint32_t a;
    asm("{ .reg .u64 t; cvta.to.shared.u64 t, %1; cvt.u32.u64 %0, t; }" : "=r"(a) : "l"(p));
    return a;
}
#define CP_ASYNC16(dst, src) \
    asm volatile("cp.async.cg.shared.global [%0], [%1], 16;" :: "r"(dst), "l"(src))
#define CP_COMMIT() asm volatile("cp.async.commit_group;" ::: "memory")
#define CP_WAIT0()  asm volatile("cp.async.wait_group 0;" ::: "memory")

#define LDSM4(r, a)                                                            \
    asm volatile("ldmatrix.sync.aligned.m8n8.x4.shared.b16 {%0,%1,%2,%3}, [%4];" \
        : "=r"((r)[0]), "=r"((r)[1]), "=r"((r)[2]), "=r"((r)[3]) : "r"(a))

__device__ __forceinline__ void mma_bf16(float* c, const uint32_t* a, const uint32_t* b) {
    asm volatile(
        "mma.sync.aligned.m16n8k16.row.col.f32.bf16.bf16.f32 "
        "{%0,%1,%2,%3}, {%4,%5,%6,%7}, {%8,%9}, {%0,%1,%2,%3};"
        : "+f"(c[0]), "+f"(c[1]), "+f"(c[2]), "+f"(c[3])
        : "r"(a[0]), "r"(a[1]), "r"(a[2]), "r"(a[3]), "r"(b[0]), "r"(b[1]));
}

__device__ __forceinline__ float ex2(float x) {
    float y;
    asm("ex2.approx.ftz.f32 %0, %1;" : "=f"(y) : "f"(x));
    return y;
}

__device__ __forceinline__ void split2(float a, float b, __nv_bfloat162& h, __nv_bfloat162& l) {
    __nv_bfloat16 ha = __float2bfloat16_rn(a), hb = __float2bfloat16_rn(b);
    h.x = ha; h.y = hb;
    l.x = __float2bfloat16_rn(a - __bfloat162float(ha));
    l.y = __float2bfloat16_rn(b - __bfloat162float(hb));
}

// ---------------- split kernel: fp32 -> bf16 hi/lo (enc + W in one launch) ----------------
__global__ void split_all(const float* __restrict__ enc, const float* __restrict__ Wm) {
    const int bx = blockIdx.x;
    if (bx < 4096) {
        int i = bx * 256 + threadIdx.x;
        float4 v = ((const float4*)enc)[i];
        __nv_bfloat162 h01, l01, h23, l23;
        split2(v.x, v.y, h01, l01);
        split2(v.z, v.w, h23, l23);
        ((__nv_bfloat162*)g_enc_h)[2 * i]     = h01;
        ((__nv_bfloat162*)g_enc_h)[2 * i + 1] = h23;
        ((__nv_bfloat162*)g_enc_l)[2 * i]     = l01;
        ((__nv_bfloat162*)g_enc_l)[2 * i + 1] = l23;
    } else {
        int i = (bx - 4096) * 256 + threadIdx.x;
        float4 v = ((const float4*)Wm)[i];
        __nv_bfloat162 h01, l01, h23, l23;
        split2(v.x, v.y, h01, l01);
        split2(v.z, v.w, h23, l23);
        ((__nv_bfloat162*)g_w_h)[2 * i]     = h01;
        ((__nv_bfloat162*)g_w_h)[2 * i + 1] = h23;
        ((__nv_bfloat162*)g_w_l)[2 * i]     = l01;
        ((__nv_bfloat162*)g_w_l)[2 * i + 1] = l23;
    }
}

// ---------------- projection GEMM: qk = enc @ W^T + bias ----------------
// Block tile 128(M) x 64(N=one head's dims), 4 warps x (32x64), K-chunk 64.
// smem buf (48KB): Ah@0 Al@16384 Bh@32768 Bl@40960 ; x2 buffers = 96KB -> 2 blocks/SM
#define PROJ_BUF 49152
#define PROJ_SMEM (2 * PROJ_BUF)

__global__ __launch_bounds__(128, 2) void proj_mma(const float* __restrict__ bias) {
    extern __shared__ char smem[];
    const int tid = threadIdx.x, l = tid & 31, w = tid >> 5;
    const int e0 = blockIdx.x * 64, m0 = blockIdx.y * 128;
    const uint32_t sb = smem_addr(smem);

    auto prefetch = [&](int buf, int k0) {
        #pragma unroll
        for (int i = 0; i < 24; i++) {
            int gi = tid + i * 128;                 // 0..3071
            const __nv_bfloat16* src;
            uint32_t dst;
            if (gi < 2048) {                        // A: 128 rows x 8 c8 x (h,l)
                int tl = gi >> 10, idx = gi & 1023, row = idx >> 3, c8 = idx & 7;
                src = (tl ? g_enc_l : g_enc_h) + (size_t)(m0 + row) * D_ + k0 + c8 * 8;
                dst = sb + buf * PROJ_BUF + tl * 16384 + SW128(row * 128 + c8 * 16);
            } else {                                // B: 64 rows x 8 c8 x (h,l)
                int gj = gi - 2048;
                int tl = gj >> 9, idx = gj & 511, row = idx >> 3, c8 = idx & 7;
                src = (tl ? g_w_l : g_w_h) + (size_t)(e0 + row) * D_ + k0 + c8 * 8;
                dst = sb + buf * PROJ_BUF + 32768 + tl * 8192 + SW128(row * 128 + c8 * 16);
            }
            CP_ASYNC16(dst, src);
        }
    };

    prefetch(0, 0);
    CP_COMMIT();

    float acc[2][8][4];
    #pragma unroll
    for (int mt = 0; mt < 2; mt++)
        #pragma unroll
        for (int nt = 0; nt < 8; nt++)
            #pragma unroll
            for (int e = 0; e < 4; e++) acc[mt][nt][e] = 0.f;

    for (int j = 0; j < 16; j++) {
        CP_WAIT0();
        __syncthreads();
        if (j < 15) { prefetch((j + 1) & 1, (j + 1) * 64); CP_COMMIT(); }

        const uint32_t tb = sb + (j & 1) * PROJ_BUF;
        #pragma unroll
        for (int s = 0; s < 4; s++) {
            const int acol = s * 32 + ((l >> 4) << 4);
            uint32_t ah[2][4], al[2][4];
            #pragma unroll
            for (int mt = 0; mt < 2; mt++) {
                const int arow = 32 * w + mt * 16 + (l & 15);
                LDSM4(ah[mt], tb + SW128(arow * 128 + acol));
                LDSM4(al[mt], tb + 16384 + SW128(arow * 128 + acol));
            }
            #pragma unroll
            for (int tp = 0; tp < 4; tp++) {
                const int brow = tp * 16 + (l & 7) + ((l >> 4) << 3);
                const int bcol = s * 32 + (((l >> 3) & 1) << 4);
                uint32_t bhf[4], blf[4];
                LDSM4(bhf, tb + 32768 + SW128(brow * 128 + bcol));
                LDSM4(blf, tb + 40960 + SW128(brow * 128 + bcol));
                #pragma unroll
                for (int mt = 0; mt < 2; mt++)
                    #pragma unroll
                    for (int nn = 0; nn < 2; nn++) {
                        float* c = acc[mt][2 * tp + nn];
                        mma_bf16(c, ah[mt], bhf + 2 * nn);
                        mma_bf16(c, ah[mt], blf + 2 * nn);
                        mma_bf16(c, al[mt], bhf + 2 * nn);
                    }
            }
        }
        __syncthreads();
    }

    // Epilogue: bias; q gets 0.125*log2(e) folded in (scores land in log2 domain).
    // e0 block = exactly one head's 64 dims.
    const bool isq = (e0 < D_);
    const int eh = isq ? e0 : e0 - D_;
    const int head = eh >> 6;
    const float scf = isq ? (0.125f * LOG2E) : 1.0f;
    __nv_bfloat16* dhb = isq ? g_qh : g_kh;
    __nv_bfloat16* dlb = isq ? g_ql : g_kl;

    #pragma unroll
    for (int mt = 0; mt < 2; mt++)
        #pragma unroll
        for (int nt = 0; nt < 8; nt++) {
            const int cp = e0 + nt * 8 + 2 * (l & 3);
            const int hd0 = cp & 63;
            const float b0 = __ldg(bias + cp), b1 = __ldg(bias + cp + 1);
            #pragma unroll
            for (int rh = 0; rh < 2; rh++) {
                const int m = m0 + 32 * w + mt * 16 + (l >> 2) + rh * 8;
                const int bb = m >> 11, s = m & (S_ - 1);
                const size_t base = (((size_t)bb * H_ + head) * S_ + s) * HD_ + hd0;
                const float v0 = (acc[mt][nt][2 * rh]     + b0) * scf;
                const float v1 = (acc[mt][nt][2 * rh + 1] + b1) * scf;
                __nv_bfloat162 h2, l2;
                split2(v0, v1, h2, l2);
                *(__nv_bfloat162*)(dhb + base) = h2;
                *(__nv_bfloat162*)(dlb + base) = l2;
            }
        }
}

// ---------------- fused attention: 4 warps x 32 q-rows, 64-row K chunks ----------------
// smem: Q hi@0 lo@16384 ; K buf b at 32768 + b*16384 (hi@0 lo@8192 within buf)
// 64KB/block -> 3 blocks/SM; acc 64 regs -> no spills.
#define ATTN_SMEM (32768 + 2 * 16384)

// 32 q-rows x 64 k-rows chunk tile for this warp: acc[mt][8 col-groups][4]
__device__ __forceinline__ void mma_chunk64(float (&acc)[2][8][4], uint32_t qb, uint32_t kb,
                                            int l, int w) {
    #pragma unroll
    for (int mt = 0; mt < 2; mt++)
        #pragma unroll
        for (int nt = 0; nt < 8; nt++)
            #pragma unroll
            for (int e = 0; e < 4; e++) acc[mt][nt][e] = 0.f;

    #pragma unroll
    for (int s = 0; s < 4; s++) {
        const int acol = s * 32 + ((l >> 4) << 4);
        uint32_t ah[2][4], al[2][4];
        #pragma unroll
        for (int mt = 0; mt < 2; mt++) {
            const int arow = 32 * w + mt * 16 + (l & 15);
            LDSM4(ah[mt], qb + SW128(arow * 128 + acol));
            LDSM4(al[mt], qb + 16384 + SW128(arow * 128 + acol));
        }
        #pragma unroll
        for (int tp = 0; tp < 4; tp++) {
            const int brow = tp * 16 + (l & 7) + ((l >> 4) << 3);
            const int bcol = s * 32 + (((l >> 3) & 1) << 4);
            uint32_t bhf[4], blf[4];
            LDSM4(bhf, kb + SW128(brow * 128 + bcol));
            LDSM4(blf, kb + 8192 + SW128(brow * 128 + bcol));
            #pragma unroll
            for (int mt = 0; mt < 2; mt++)
                #pragma unroll
                for (int nn = 0; nn < 2; nn++) {
                    float* c = acc[mt][2 * tp + nn];
                    mma_bf16(c, ah[mt], bhf + 2 * nn);
                    mma_bf16(c, ah[mt], blf + 2 * nn);
                    mma_bf16(c, al[mt], bhf + 2 * nn);
                }
        }
    }
}

__global__ __launch_bounds__(128, 3) void attn_fused(float* __restrict__ out) {
    extern __shared__ char smem[];
    const int tid = threadIdx.x, l = tid & 31, w = tid >> 5;
    const int bx = 15 - blockIdx.x;                // big tiles launch first
    const int t0 = bx * 128;
    const int bh = blockIdx.z * H_ + blockIdx.y;
    const uint32_t sb = smem_addr(smem);

    const __nv_bfloat16* qh = g_qh + ((size_t)bh * S_ + t0) * HD_;
    const __nv_bfloat16* ql = g_ql + ((size_t)bh * S_ + t0) * HD_;
    const __nv_bfloat16* khb = g_kh + (size_t)bh * S_ * HD_;
    const __nv_bfloat16* klb = g_kl + (size_t)bh * S_ * HD_;

    auto prefetch_k = [&](int buf, int chunk) {      // 64-row chunk: 16KB
        const __nv_bfloat16* kh = khb + (size_t)chunk * 64 * HD_;
        const __nv_bfloat16* kl = klb + (size_t)chunk * 64 * HD_;
        #pragma unroll
        for (int i = 0; i < 8; i++) {
            int gi = tid + i * 128;
            int tl = gi >> 9, idx = gi & 511, row = idx >> 3, c8 = idx & 7;
            CP_ASYNC16(sb + 32768 + buf * 16384 + tl * 8192 + SW128(row * 128 + c8 * 16),
                       (tl ? kl : kh) + row * HD_ + c8 * 8);
        }
    };

    // Q (persistent, 32KB) + K chunk 0
    #pragma unroll
    for (int i = 0; i < 16; i++) {
        int gi = tid + i * 128;
        int tl = gi >> 10, idx = gi & 1023, row = idx >> 3, c8 = idx & 7;
        CP_ASYNC16(sb + tl * 16384 + SW128(row * 128 + c8 * 16),
                   (tl ? ql : qh) + row * HD_ + c8 * 8);
    }
    prefetch_k(0, 0);
    CP_COMMIT();

    const int rq = (l >> 2);                       // quad row within 8
    const int nj = 2 * bx + 2;                     // causal 64-col chunks
    float d[2][2] = {{0.f, 0.f}, {0.f, 0.f}};      // [mt][rowhalf] sums of 2^score

    // ---- phase A: row sums ----
    for (int j = 0; j < nj; j++) {
        CP_WAIT0();
        __syncthreads();
        prefetch_k((j + 1) & 1, (j + 1 < nj) ? j + 1 : 0);   // wraps to phase-B chunk 0
        CP_COMMIT();

        const uint32_t kb = sb + 32768 + (j & 1) * 16384;
        float acc[2][8][4];
        mma_chunk64(acc, sb, kb, l, w);

        const bool diag = (j >= 2 * bx);
        const int coff = (j - 2 * bx) * 64;        // column offset vs local rows (valid if diag)
        #pragma unroll
        for (int mt = 0; mt < 2; mt++) {
            const int rr0 = 32 * w + 16 * mt + rq, rr1 = rr0 + 8;
            #pragma unroll
            for (int nt = 0; nt < 8; nt++)
                #pragma unroll
                for (int e = 0; e < 2; e++) {
                    const int cl = nt * 8 + 2 * (l & 3) + e;
                    float e0 = ex2(acc[mt][nt][e]);
                    float e1 = ex2(acc[mt][nt][2 + e]);
                    if (diag) {
                        if (coff + cl > rr0) e0 = 0.f;
                        if (coff + cl > rr1) e1 = 0.f;
                    }
                    d[mt][0] += e0; d[mt][1] += e1;
                }
        }
    }

    // full row sum lives in the 4 lanes of each quad
    #pragma unroll
    for (int off = 1; off <= 2; off <<= 1) {
        #pragma unroll
        for (int mt = 0; mt < 2; mt++) {
            d[mt][0] += __shfl_xor_sync(0xffffffffu, d[mt][0], off);
            d[mt][1] += __shfl_xor_sync(0xffffffffu, d[mt][1], off);
        }
    }
    float vi[2][2];
    #pragma unroll
    for (int mt = 0; mt < 2; mt++) {
        vi[mt][0] = 1.f / d[mt][0];
        vi[mt][1] = 1.f / d[mt][1];
    }

    // ---- phase B: probabilities ----
    for (int j = 0; j < nj; j++) {
        CP_WAIT0();
        __syncthreads();
        if (j + 1 < nj) { prefetch_k((nj + j + 1) & 1, j + 1); CP_COMMIT(); }

        const uint32_t kb = sb + 32768 + ((nj + j) & 1) * 16384;
        float acc[2][8][4];
        mma_chunk64(acc, sb, kb, l, w);

        const bool diag = (j >= 2 * bx);
        const int coff = (j - 2 * bx) * 64;
        #pragma unroll
        for (int mt = 0; mt < 2; mt++) {
            const int rr0 = 32 * w + 16 * mt + rq, rr1 = rr0 + 8;
            float* o0 = out + ((size_t)bh * S_ + t0 + rr0) * S_ + j * 64 + 2 * (l & 3);
            float* o1 = out + ((size_t)bh * S_ + t0 + rr1) * S_ + j * 64 + 2 * (l & 3);
            #pragma unroll
            for (int nt = 0; nt < 8; nt++) {
                const int cl = nt * 8 + 2 * (l & 3);
                float2 p0, p1;
                p0.x = ex2(acc[mt][nt][0]) * vi[mt][0];
                p0.y = ex2(acc[mt][nt][1]) * vi[mt][0];
                p1.x = ex2(acc[mt][nt][2]) * vi[mt][1];
                p1.y = ex2(acc[mt][nt][3]) * vi[mt][1];
                if (diag) {
                    if (coff + cl     > rr0) p0.x = 0.f;
                    if (coff + cl + 1 > rr0) p0.y = 0.f;
                    if (coff + cl     > rr1) p1.x = 0.f;
                    if (coff + cl + 1 > rr1) p1.y = 0.f;
                }
                __stcs((float2*)(o0 + nt * 8), p0);
                __stcs((float2*)(o1 + nt * 8), p1);
            }
        }
    }

    // zero-fill strictly-future columns (one row per thread)
    const int cbase = 64 * nj;                     // == 128*(bx+1)
    const int len = S_ - cbase;
    if (len > 0) {
        float4* p = (float4*)(out + ((size_t)bh * S_ + t0 + tid) * S_ + cbase);
        const int n4 = len >> 2;
        const float4 z = make_float4(0.f, 0.f, 0.f, 0.f);
        for (int i = 0; i < n4; i++) __stcs(p + i, z);
    }
}

// ---------------------------------------------------------------------------
extern "C" void kernel_launch(void* const* d_in, const int* in_sizes, int n_in,
                              void* d_out, int out_size)
{
    (void)in_sizes; (void)n_in; (void)out_size;
    const float* encoded = (const float*)d_in[0];  // [2, 2048, 1024]
    const float* W       = (const float*)d_in[1];  // [2048, 1024]
    const float* bias    = (const float*)d_in[2];  // [2048]
    float* out = (float*)d_out;                    // [2, 16, 2048, 2048]

    cudaFuncSetAttribute(proj_mma,   cudaFuncAttributeMaxDynamicSharedMemorySize, PROJ_SMEM);
    cudaFuncSetAttribute(attn_fused, cudaFuncAttributeMaxDynamicSharedMemorySize, ATTN_SMEM);

    split_all<<<6144, 256>>>(encoded, W);
    proj_mma<<<dim3(32, 32), 128, PROJ_SMEM>>>(bias);
    attn_fused<<<dim3(16, H_, B_), 128, ATTN_SMEM>>>(out);
}